// round 9
// baseline (speedup 1.0000x reference)
#include <cuda_runtime.h>
#include <cuda_bf16.h>

#define N_NODES 100000
#define N_EDGES 1600000
#define EMBED 64
#define HEADS 8
#define FFN_DIM 256
#define LN_EPS 1e-5f
#define CAP 128

typedef unsigned long long u64;

// ---------------- f32x2 packed math ----------------
__device__ __forceinline__ u64 pack2(float lo, float hi) {
    u64 r; asm("mov.b64 %0,{%1,%2};" : "=l"(r) : "f"(lo), "f"(hi)); return r;
}
__device__ __forceinline__ void unpack2(u64 v, float& lo, float& hi) {
    asm("mov.b64 {%0,%1},%2;" : "=f"(lo), "=f"(hi) : "l"(v));
}
__device__ __forceinline__ u64 fma2(u64 a, u64 b, u64 c) {
    u64 d; asm("fma.rn.f32x2 %0,%1,%2,%3;" : "=l"(d) : "l"(a), "l"(b), "l"(c)); return d;
}
__device__ __forceinline__ float hadd2(u64 v) {
    float a, b; unpack2(v, a, b); return a + b;
}
__device__ __forceinline__ ulonglong2 lds128(const void* p) {
    ulonglong2 v;
    asm("ld.shared.v2.u64 {%0,%1}, [%2];"
        : "=l"(v.x), "=l"(v.y) : "l"((u64)__cvta_generic_to_shared(p)));
    return v;
}

// ---------------- scratch ----------------
__device__ float g_q[N_NODES * EMBED];
__device__ float g_k[N_NODES * EMBED];
__device__ float g_v[N_NODES * EMBED];
__device__ float g_x1[N_NODES * EMBED];
__device__ float g_hid[N_NODES * FFN_DIM];
__device__ int   g_cnt[N_NODES];
__device__ int   g_bcol[N_NODES * CAP];
__device__ int   g_is64;

// GEMM inner block: 4 LDS.128 -> 32 FFMA2 for 4 channels over a 16-wide k slice
__device__ __forceinline__ void gemm16x4(const float* xa, const u64 wd[4][8], u64 a[4]) {
    ulonglong2 v0 = lds128(xa), v1 = lds128(xa + 4), v2 = lds128(xa + 8), v3 = lds128(xa + 12);
    u64 xu[8] = {v0.x, v0.y, v1.x, v1.y, v2.x, v2.y, v3.x, v3.y};
#pragma unroll
    for (int j = 0; j < 8; j++) {
#pragma unroll
        for (int ch = 0; ch < 4; ch++) a[ch] = fma2(xu[j], wd[ch][j], a[ch]);
    }
}

// ---------------- QKV: 8 nodes/iter, butterfly reduce, double-buffered ----------------
// thread: kp = t&3 (k-slice of 16), cp = t>>2 (channels 4cp..4cp+3); after xor-1,2
// reduction thread t owns channel t of 192.
__global__ __launch_bounds__(192, 2) void k_qkv(const float* __restrict__ x,
                                                const float* __restrict__ w,
                                                const float* __restrict__ b,
                                                const void* __restrict__ ei) {
    int t = threadIdx.x;
    for (int gi = blockIdx.x * 192 + t; gi < N_NODES; gi += gridDim.x * 192) g_cnt[gi] = 0;
    if (blockIdx.x == 0 && t == 0) {
        const unsigned* wr = (const unsigned*)ei;
        int is64 = 1;
        for (int q = 1; q < 256; q += 2) if (wr[q] != 0u) { is64 = 0; break; }
        g_is64 = is64;
    }
    __shared__ __align__(16) float xs[2][512];
    int kp = t & 3, cp = t >> 2, sel = kp;
    u64 wd[4][8];
#pragma unroll
    for (int ch = 0; ch < 4; ch++)
#pragma unroll
        for (int j = 0; j < 8; j++)
            wd[ch][j] = pack2(w[(kp * 16 + 2 * j) * 192 + 4 * cp + ch],
                              w[(kp * 16 + 2 * j + 1) * 192 + 4 * cp + ch]);
    float bias = b[t];
    int h = t / 24, r = t % 24;
    float* dst = (r < 8) ? g_q : (r < 16 ? g_k : g_v);
    int off = h * 8 + (r & 7);

    const int ngrp = N_NODES / 8;
    const int stride = gridDim.x;
    int p = blockIdx.x;
    if (p < ngrp && t < 128) ((float4*)xs[0])[t] = ((const float4*)(x + p * 8 * 64))[t];
    __syncthreads();
    for (int it = 0; p < ngrp; p += stride, it ^= 1) {
        int pn = p + stride;
        float4 nx;
        if (t < 128 && pn < ngrp) nx = ((const float4*)(x + pn * 8 * 64))[t];
        int n0 = 8 * p;
#pragma unroll
        for (int n = 0; n < 8; n++) {
            u64 a[4] = {0ull, 0ull, 0ull, 0ull};
            gemm16x4(xs[it] + n * 64 + kp * 16, wd, a);
            float v0 = hadd2(a[0]), v1 = hadd2(a[1]), v2 = hadd2(a[2]), v3 = hadd2(a[3]);
            v0 += __shfl_xor_sync(~0u, v0, 1); v0 += __shfl_xor_sync(~0u, v0, 2);
            v1 += __shfl_xor_sync(~0u, v1, 1); v1 += __shfl_xor_sync(~0u, v1, 2);
            v2 += __shfl_xor_sync(~0u, v2, 1); v2 += __shfl_xor_sync(~0u, v2, 2);
            v3 += __shfl_xor_sync(~0u, v3, 1); v3 += __shfl_xor_sync(~0u, v3, 2);
            float val = (sel == 0) ? v0 : (sel == 1) ? v1 : (sel == 2) ? v2 : v3;
            dst[(n0 + n) * 64 + off] = bias + val;
        }
        if (t < 128 && pn < ngrp) ((float4*)xs[it ^ 1])[t] = nx;
        __syncthreads();
    }
}

// ---------------- bucket scatter ----------------
__global__ void k_scatter(const void* __restrict__ ei_raw) {
    int e = blockIdx.x * blockDim.x + threadIdx.x;
    if (e >= N_EDGES) return;
    int r, c;
    if (g_is64) {
        const long long* ei = (const long long*)ei_raw;
        r = (int)ei[e]; c = (int)ei[N_EDGES + e];
    } else {
        const int* ei = (const int*)ei_raw;
        r = ei[e]; c = ei[N_EDGES + e];
    }
    int slot = atomicAdd(&g_cnt[r], 1);
    if (slot < CAP) g_bcol[r * CAP + slot] = c;
}

// ---------------- gather attention + residual + LN1 ----------------
__global__ __launch_bounds__(256) void k_gather(const float* __restrict__ x,
                                                const float* __restrict__ lg,
                                                const float* __restrict__ lb) {
    int t = threadIdx.x;
    int n = blockIdx.x * 32 + (t >> 3);
    int h = t & 7;
    const int base = n * 64 + h * 8;
    const float4* qp = (const float4*)(g_q + base);
    float4 q0 = qp[0], q1 = qp[1];

    int deg = g_cnt[n];
    if (deg > CAP) deg = CAP;

    float den = 0.f;
    float4 a0 = make_float4(0.f, 0.f, 0.f, 0.f);
    float4 a1 = make_float4(0.f, 0.f, 0.f, 0.f);

    const int* bp = g_bcol + n * CAP;
    int cnext = (deg > 0) ? bp[0] : 0;
    for (int s = 0; s < deg; s++) {
        int c = cnext;
        cnext = (s + 1 < deg) ? bp[s + 1] : 0;
        const float4* kp = (const float4*)(g_k + c * 64 + h * 8);
        const float4* vp = (const float4*)(g_v + c * 64 + h * 8);
        float4 k0 = kp[0], k1 = kp[1];
        float4 v0 = vp[0], v1 = vp[1];
        float dot = q0.x * k0.x + q0.y * k0.y + q0.z * k0.z + q0.w * k0.w
                  + q1.x * k1.x + q1.y * k1.y + q1.z * k1.z + q1.w * k1.w;
        float ew = __expf(dot * 0.125f);
        den += ew;
        a0.x += ew * v0.x; a0.y += ew * v0.y; a0.z += ew * v0.z; a0.w += ew * v0.w;
        a1.x += ew * v1.x; a1.y += ew * v1.y; a1.z += ew * v1.z; a1.w += ew * v1.w;
    }
    float inv = (den > 0.f) ? (1.f / den) : 0.f;

    const float4* xp = (const float4*)(x + base);
    float4 x0 = xp[0], x1 = xp[1];
    float s_[8];
    s_[0] = x0.x + a0.x * inv; s_[1] = x0.y + a0.y * inv;
    s_[2] = x0.z + a0.z * inv; s_[3] = x0.w + a0.w * inv;
    s_[4] = x1.x + a1.x * inv; s_[5] = x1.y + a1.y * inv;
    s_[6] = x1.z + a1.z * inv; s_[7] = x1.w + a1.w * inv;
    float sum = 0.f, sq = 0.f;
#pragma unroll
    for (int j = 0; j < 8; j++) { sum += s_[j]; sq += s_[j] * s_[j]; }
#pragma unroll
    for (int o = 4; o; o >>= 1) {
        sum += __shfl_xor_sync(0xffffffffu, sum, o);
        sq  += __shfl_xor_sync(0xffffffffu, sq, o);
    }
    float mean = sum * (1.f / 64.f);
    float var = sq * (1.f / 64.f) - mean * mean;
    float rstd = rsqrtf(var + LN_EPS);
    float4 y0, y1;
    int c0 = h * 8;
    y0.x = (s_[0] - mean) * rstd * lg[c0 + 0] + lb[c0 + 0];
    y0.y = (s_[1] - mean) * rstd * lg[c0 + 1] + lb[c0 + 1];
    y0.z = (s_[2] - mean) * rstd * lg[c0 + 2] + lb[c0 + 2];
    y0.w = (s_[3] - mean) * rstd * lg[c0 + 3] + lb[c0 + 3];
    y1.x = (s_[4] - mean) * rstd * lg[c0 + 4] + lb[c0 + 4];
    y1.y = (s_[5] - mean) * rstd * lg[c0 + 5] + lb[c0 + 5];
    y1.z = (s_[6] - mean) * rstd * lg[c0 + 6] + lb[c0 + 6];
    y1.w = (s_[7] - mean) * rstd * lg[c0 + 7] + lb[c0 + 7];
    float4* op = (float4*)(g_x1 + base);
    op[0] = y0; op[1] = y1;
}

// ---------------- FFN GEMM1: butterfly reduce, double-buffered ----------------
// thread: kp = t&3 (k-slice 16), cp = t>>2 (channels 4cp..4cp+3); owns channel t after reduce
__global__ __launch_bounds__(256, 2) void k_ffn1(const float* __restrict__ w1,
                                                 const float* __restrict__ b1) {
    __shared__ __align__(16) float xs[2][512];
    int t = threadIdx.x;
    int kp = t & 3, cp = t >> 2, sel = kp;
    u64 wd[4][8];
#pragma unroll
    for (int ch = 0; ch < 4; ch++)
#pragma unroll
        for (int j = 0; j < 8; j++)
            wd[ch][j] = pack2(w1[(kp * 16 + 2 * j) * 256 + 4 * cp + ch],
                              w1[(kp * 16 + 2 * j + 1) * 256 + 4 * cp + ch]);
    float b1t = b1[t];

    const int ngrp = N_NODES / 8;
    const int stride = gridDim.x;
    int p = blockIdx.x;
    if (p < ngrp && t < 128) ((float4*)xs[0])[t] = ((const float4*)(g_x1 + p * 8 * 64))[t];
    __syncthreads();
    for (int it = 0; p < ngrp; p += stride, it ^= 1) {
        int pn = p + stride;
        float4 nx;
        if (t < 128 && pn < ngrp) nx = ((const float4*)(g_x1 + pn * 8 * 64))[t];
        int n0 = 8 * p;
#pragma unroll
        for (int n = 0; n < 8; n++) {
            u64 a[4] = {0ull, 0ull, 0ull, 0ull};
            gemm16x4(xs[it] + n * 64 + kp * 16, wd, a);
            float v0 = hadd2(a[0]), v1 = hadd2(a[1]), v2 = hadd2(a[2]), v3 = hadd2(a[3]);
            v0 += __shfl_xor_sync(~0u, v0, 1); v0 += __shfl_xor_sync(~0u, v0, 2);
            v1 += __shfl_xor_sync(~0u, v1, 1); v1 += __shfl_xor_sync(~0u, v1, 2);
            v2 += __shfl_xor_sync(~0u, v2, 1); v2 += __shfl_xor_sync(~0u, v2, 2);
            v3 += __shfl_xor_sync(~0u, v3, 1); v3 += __shfl_xor_sync(~0u, v3, 2);
            float val = (sel == 0) ? v0 : (sel == 1) ? v1 : (sel == 2) ? v2 : v3;
            g_hid[(n0 + n) * 256 + t] = fmaxf(val + b1t, 0.f);
        }
        if (t < 128 && pn < ngrp) ((float4*)xs[it ^ 1])[t] = nx;
        __syncthreads();
    }
}

// ---------------- FFN GEMM2: 16-way k-split butterfly + residual + LN2 ----------------
// thread: kp = t&15 (k-slice 16 of 256), cp = t>>4 (channels 4cp..4cp+3 of 64)
__global__ __launch_bounds__(256, 2) void k_ffn2(const float* __restrict__ w2,
                                                 const float* __restrict__ b2,
                                                 const float* __restrict__ lg,
                                                 const float* __restrict__ lb,
                                                 float* __restrict__ out) {
    __shared__ __align__(16) float xs[2][512];
    __shared__ __align__(16) float hs[2][2048];
    __shared__ __align__(16) float osum[8][64];
    int t = threadIdx.x;
    int kp = t & 15, cp = t >> 4;
    int wnode = t >> 5, l = t & 31;
    u64 wd[4][8];
#pragma unroll
    for (int ch = 0; ch < 4; ch++)
#pragma unroll
        for (int j = 0; j < 8; j++)
            wd[ch][j] = pack2(w2[(kp * 16 + 2 * j) * 64 + 4 * cp + ch],
                              w2[(kp * 16 + 2 * j + 1) * 64 + 4 * cp + ch]);
    float b2A = b2[l], b2B = b2[l + 32];
    float gA = lg[l], gB = lg[l + 32], bA = lb[l], bB = lb[l + 32];
    bool writer = (kp < 4);
    int wch = 4 * cp + kp;   // valid when writer

    const int ngrp = N_NODES / 8;
    const int stride = gridDim.x;
    int p = blockIdx.x;
    if (p < ngrp) {
        if (t < 128) ((float4*)xs[0])[t] = ((const float4*)(g_x1 + p * 8 * 64))[t];
        ((float4*)hs[0])[t]       = ((const float4*)(g_hid + p * 8 * 256))[t];
        ((float4*)hs[0])[t + 256] = ((const float4*)(g_hid + p * 8 * 256))[t + 256];
    }
    __syncthreads();
    for (int it = 0; p < ngrp; p += stride, it ^= 1) {
        int pn = p + stride;
        float4 nx, nh0, nh1;
        if (pn < ngrp) {
            if (t < 128) nx = ((const float4*)(g_x1 + pn * 8 * 64))[t];
            nh0 = ((const float4*)(g_hid + pn * 8 * 256))[t];
            nh1 = ((const float4*)(g_hid + pn * 8 * 256))[t + 256];
        }
        int n0 = 8 * p;
#pragma unroll
        for (int n = 0; n < 8; n++) {
            u64 a[4] = {0ull, 0ull, 0ull, 0ull};
            gemm16x4(hs[it] + n * 256 + kp * 16, wd, a);
            float v0 = hadd2(a[0]), v1 = hadd2(a[1]), v2 = hadd2(a[2]), v3 = hadd2(a[3]);
#pragma unroll
            for (int m = 1; m < 16; m <<= 1) {
                v0 += __shfl_xor_sync(~0u, v0, m);
                v1 += __shfl_xor_sync(~0u, v1, m);
                v2 += __shfl_xor_sync(~0u, v2, m);
                v3 += __shfl_xor_sync(~0u, v3, m);
            }
            if (writer) {
                float val = (kp == 0) ? v0 : (kp == 1) ? v1 : (kp == 2) ? v2 : v3;
                osum[n][wch] = val;
            }
        }
        __syncthreads();
        // epilogue: warp wnode -> node wnode; lane l -> channels l, l+32
        {
            float vA = xs[it][wnode * 64 + l]      + osum[wnode][l]      + b2A;
            float vB = xs[it][wnode * 64 + l + 32] + osum[wnode][l + 32] + b2B;
            float sum = vA + vB, sq = vA * vA + vB * vB;
#pragma unroll
            for (int o = 16; o; o >>= 1) {
                sum += __shfl_xor_sync(0xffffffffu, sum, o);
                sq  += __shfl_xor_sync(0xffffffffu, sq, o);
            }
            float mean = sum * (1.f / 64.f);
            float var = sq * (1.f / 64.f) - mean * mean;
            float rstd = rsqrtf(var + LN_EPS);
            out[(n0 + wnode) * 64 + l]      = (vA - mean) * rstd * gA + bA;
            out[(n0 + wnode) * 64 + l + 32] = (vB - mean) * rstd * gB + bB;
        }
        if (pn < ngrp) {
            if (t < 128) ((float4*)xs[it ^ 1])[t] = nx;
            ((float4*)hs[it ^ 1])[t]       = nh0;
            ((float4*)hs[it ^ 1])[t + 256] = nh1;
        }
        __syncthreads();
    }
}

extern "C" void kernel_launch(void* const* d_in, const int* in_sizes, int n_in,
                              void* d_out, int out_size) {
    const float* x      = (const float*)d_in[0];
    const void*  ei     = d_in[1];
    const float* attn_w = (const float*)d_in[2];
    const float* attn_b = (const float*)d_in[3];
    const float* w1     = (const float*)d_in[4];
    const float* b1     = (const float*)d_in[5];
    const float* w2     = (const float*)d_in[6];
    const float* b2     = (const float*)d_in[7];
    const float* ln1_g  = (const float*)d_in[8];
    const float* ln1_b  = (const float*)d_in[9];
    const float* ln2_g  = (const float*)d_in[10];
    const float* ln2_b  = (const float*)d_in[11];
    float* out = (float*)d_out;

    k_qkv<<<296, 192>>>(x, attn_w, attn_b, ei);
    k_scatter<<<N_EDGES / 256, 256>>>(ei);
    k_gather<<<N_NODES / 32, 256>>>(x, ln1_g, ln1_b);
    k_ffn1<<<296, 256>>>(w1, b1);
    k_ffn2<<<296, 256>>>(w2, b2, ln2_g, ln2_b, out);
}

// round 10
// speedup vs baseline: 1.6877x; 1.6877x over previous
#include <cuda_runtime.h>
#include <cuda_bf16.h>

#define N_NODES 100000
#define N_EDGES 1600000
#define EMBED 64
#define HEADS 8
#define FFN_DIM 256
#define LN_EPS 1e-5f
#define CAP 128

typedef unsigned long long u64;

// ---------------- f32x2 packed math ----------------
__device__ __forceinline__ u64 pack2(float lo, float hi) {
    u64 r; asm("mov.b64 %0,{%1,%2};" : "=l"(r) : "f"(lo), "f"(hi)); return r;
}
__device__ __forceinline__ void unpack2(u64 v, float& lo, float& hi) {
    asm("mov.b64 {%0,%1},%2;" : "=f"(lo), "=f"(hi) : "l"(v));
}
__device__ __forceinline__ u64 fma2(u64 a, u64 b, u64 c) {
    u64 d; asm("fma.rn.f32x2 %0,%1,%2,%3;" : "=l"(d) : "l"(a), "l"(b), "l"(c)); return d;
}
__device__ __forceinline__ float hadd2(u64 v) {
    float a, b; unpack2(v, a, b); return a + b;
}
__device__ __forceinline__ ulonglong2 lds128(const void* p) {
    ulonglong2 v;
    asm("ld.shared.v2.u64 {%0,%1}, [%2];"
        : "=l"(v.x), "=l"(v.y) : "l"((u64)__cvta_generic_to_shared(p)));
    return v;
}

// ---------------- scratch ----------------
__device__ float g_q[N_NODES * EMBED];
__device__ float g_k[N_NODES * EMBED];
__device__ float g_v[N_NODES * EMBED];
__device__ float g_x1[N_NODES * EMBED];
__device__ float g_hid[N_NODES * FFN_DIM];
__device__ int   g_cnt[N_NODES];
__device__ int   g_bcol[N_NODES * CAP];
__device__ int   g_is64;

// GEMM inner block: 4 LDS.128 -> 32 FFMA2 for 4 channels over a 16-wide k slice
__device__ __forceinline__ void gemm16x4(const float* xa, const u64 wd[4][8], u64 a[4]) {
    ulonglong2 v0 = lds128(xa), v1 = lds128(xa + 4), v2 = lds128(xa + 8), v3 = lds128(xa + 12);
    u64 xu[8] = {v0.x, v0.y, v1.x, v1.y, v2.x, v2.y, v3.x, v3.y};
#pragma unroll
    for (int j = 0; j < 8; j++) {
#pragma unroll
        for (int ch = 0; ch < 4; ch++) a[ch] = fma2(xu[j], wd[ch][j], a[ch]);
    }
}

// ---------------- QKV: 4 ch/thread, 4-way k-split, psum reduce, double-buffered ----------------
// thread: cp = t%48 (channels 4cp..4cp+3 of 192), kp = t/48 (k-slice [kp*16,+16))
__global__ __launch_bounds__(192, 2) void k_qkv(const float* __restrict__ x,
                                                const float* __restrict__ w,
                                                const float* __restrict__ b,
                                                const void* __restrict__ ei) {
    int t = threadIdx.x;
    for (int gi = blockIdx.x * 192 + t; gi < N_NODES; gi += gridDim.x * 192) g_cnt[gi] = 0;
    if (blockIdx.x == 0 && t == 0) {
        const unsigned* wr = (const unsigned*)ei;
        int is64 = 1;
        for (int q = 1; q < 256; q += 2) if (wr[q] != 0u) { is64 = 0; break; }
        g_is64 = is64;
    }
    __shared__ __align__(16) float xs[2][512];
    __shared__ __align__(16) float psum[8][4][192];   // 24 kB
    int cp = t % 48, kp = t / 48;
    int c0 = 4 * cp;
    u64 wd[4][8];
#pragma unroll
    for (int ch = 0; ch < 4; ch++)
#pragma unroll
        for (int j = 0; j < 8; j++)
            wd[ch][j] = pack2(w[(kp * 16 + 2 * j) * 192 + c0 + ch],
                              w[(kp * 16 + 2 * j + 1) * 192 + c0 + ch]);
    float bias = b[t];
    int h = t / 24, r = t % 24;
    float* dst = (r < 8) ? g_q : (r < 16 ? g_k : g_v);
    int off = h * 8 + (r & 7);

    const int ngrp = N_NODES / 8;
    const int stride = gridDim.x;
    int p = blockIdx.x;
    if (p < ngrp && t < 128) ((float4*)xs[0])[t] = ((const float4*)(x + p * 8 * 64))[t];
    __syncthreads();
    for (int it = 0; p < ngrp; p += stride, it ^= 1) {
        int pn = p + stride;
        float4 nx;
        if (t < 128 && pn < ngrp) nx = ((const float4*)(x + pn * 8 * 64))[t];
        int n0 = 8 * p;
#pragma unroll
        for (int n = 0; n < 8; n++) {
            u64 a[4] = {0ull, 0ull, 0ull, 0ull};
            gemm16x4(xs[it] + n * 64 + kp * 16, wd, a);
            *(float4*)&psum[n][kp][c0] =
                make_float4(hadd2(a[0]), hadd2(a[1]), hadd2(a[2]), hadd2(a[3]));
        }
        __syncthreads();
#pragma unroll
        for (int n = 0; n < 8; n++) {
            float v = psum[n][0][t] + psum[n][1][t] + psum[n][2][t] + psum[n][3][t];
            dst[(n0 + n) * 64 + off] = bias + v;
        }
        if (t < 128 && pn < ngrp) ((float4*)xs[it ^ 1])[t] = nx;
        __syncthreads();
    }
}

// ---------------- bucket scatter ----------------
__global__ void k_scatter(const void* __restrict__ ei_raw) {
    int e = blockIdx.x * blockDim.x + threadIdx.x;
    if (e >= N_EDGES) return;
    int r, c;
    if (g_is64) {
        const long long* ei = (const long long*)ei_raw;
        r = (int)ei[e]; c = (int)ei[N_EDGES + e];
    } else {
        const int* ei = (const int*)ei_raw;
        r = ei[e]; c = ei[N_EDGES + e];
    }
    int slot = atomicAdd(&g_cnt[r], 1);
    if (slot < CAP) g_bcol[r * CAP + slot] = c;
}

// ---------------- gather attention + residual + LN1 ----------------
__global__ __launch_bounds__(256) void k_gather(const float* __restrict__ x,
                                                const float* __restrict__ lg,
                                                const float* __restrict__ lb) {
    int t = threadIdx.x;
    int n = blockIdx.x * 32 + (t >> 3);
    int h = t & 7;
    const int base = n * 64 + h * 8;
    const float4* qp = (const float4*)(g_q + base);
    float4 q0 = qp[0], q1 = qp[1];

    int deg = g_cnt[n];
    if (deg > CAP) deg = CAP;

    float den = 0.f;
    float4 a0 = make_float4(0.f, 0.f, 0.f, 0.f);
    float4 a1 = make_float4(0.f, 0.f, 0.f, 0.f);

    const int* bp = g_bcol + n * CAP;
    int cnext = (deg > 0) ? bp[0] : 0;
    for (int s = 0; s < deg; s++) {
        int c = cnext;
        cnext = (s + 1 < deg) ? bp[s + 1] : 0;
        const float4* kp = (const float4*)(g_k + c * 64 + h * 8);
        const float4* vp = (const float4*)(g_v + c * 64 + h * 8);
        float4 k0 = kp[0], k1 = kp[1];
        float4 v0 = vp[0], v1 = vp[1];
        float dot = q0.x * k0.x + q0.y * k0.y + q0.z * k0.z + q0.w * k0.w
                  + q1.x * k1.x + q1.y * k1.y + q1.z * k1.z + q1.w * k1.w;
        float ew = __expf(dot * 0.125f);
        den += ew;
        a0.x += ew * v0.x; a0.y += ew * v0.y; a0.z += ew * v0.z; a0.w += ew * v0.w;
        a1.x += ew * v1.x; a1.y += ew * v1.y; a1.z += ew * v1.z; a1.w += ew * v1.w;
    }
    float inv = (den > 0.f) ? (1.f / den) : 0.f;

    const float4* xp = (const float4*)(x + base);
    float4 x0 = xp[0], x1 = xp[1];
    float s_[8];
    s_[0] = x0.x + a0.x * inv; s_[1] = x0.y + a0.y * inv;
    s_[2] = x0.z + a0.z * inv; s_[3] = x0.w + a0.w * inv;
    s_[4] = x1.x + a1.x * inv; s_[5] = x1.y + a1.y * inv;
    s_[6] = x1.z + a1.z * inv; s_[7] = x1.w + a1.w * inv;
    float sum = 0.f, sq = 0.f;
#pragma unroll
    for (int j = 0; j < 8; j++) { sum += s_[j]; sq += s_[j] * s_[j]; }
#pragma unroll
    for (int o = 4; o; o >>= 1) {
        sum += __shfl_xor_sync(0xffffffffu, sum, o);
        sq  += __shfl_xor_sync(0xffffffffu, sq, o);
    }
    float mean = sum * (1.f / 64.f);
    float var = sq * (1.f / 64.f) - mean * mean;
    float rstd = rsqrtf(var + LN_EPS);
    float4 y0, y1;
    int c0 = h * 8;
    y0.x = (s_[0] - mean) * rstd * lg[c0 + 0] + lb[c0 + 0];
    y0.y = (s_[1] - mean) * rstd * lg[c0 + 1] + lb[c0 + 1];
    y0.z = (s_[2] - mean) * rstd * lg[c0 + 2] + lb[c0 + 2];
    y0.w = (s_[3] - mean) * rstd * lg[c0 + 3] + lb[c0 + 3];
    y1.x = (s_[4] - mean) * rstd * lg[c0 + 4] + lb[c0 + 4];
    y1.y = (s_[5] - mean) * rstd * lg[c0 + 5] + lb[c0 + 5];
    y1.z = (s_[6] - mean) * rstd * lg[c0 + 6] + lb[c0 + 6];
    y1.w = (s_[7] - mean) * rstd * lg[c0 + 7] + lb[c0 + 7];
    float4* op = (float4*)(g_x1 + base);
    op[0] = y0; op[1] = y1;
}

// ---------------- FFN GEMM1: psum form + double-buffered tiles ----------------
// thread (kp = t>>6 in [0,4), cp = t&63): k-slice [kp*16,+16), channels 4cp..4cp+3
__global__ __launch_bounds__(256, 2) void k_ffn1(const float* __restrict__ w1,
                                                 const float* __restrict__ b1) {
    __shared__ __align__(16) float xs[2][512];
    __shared__ __align__(16) float psum[8][4][256];   // 32 kB
    int t = threadIdx.x;
    int kp = t >> 6, cp = t & 63;
    int c0 = 4 * cp;
    u64 w1d[4][8];
#pragma unroll
    for (int ch = 0; ch < 4; ch++)
#pragma unroll
        for (int j = 0; j < 8; j++)
            w1d[ch][j] = pack2(w1[(kp * 16 + 2 * j) * 256 + c0 + ch],
                               w1[(kp * 16 + 2 * j + 1) * 256 + c0 + ch]);
    float b1t = b1[t];

    const int ngrp = N_NODES / 8;
    const int stride = gridDim.x;
    int p = blockIdx.x;
    if (p < ngrp && t < 128) ((float4*)xs[0])[t] = ((const float4*)(g_x1 + p * 8 * 64))[t];
    __syncthreads();
    for (int it = 0; p < ngrp; p += stride, it ^= 1) {
        int pn = p + stride;
        float4 nx;
        if (t < 128 && pn < ngrp) nx = ((const float4*)(g_x1 + pn * 8 * 64))[t];
        int n0 = 8 * p;
#pragma unroll
        for (int n = 0; n < 8; n++) {
            u64 a[4] = {0ull, 0ull, 0ull, 0ull};
            gemm16x4(xs[it] + n * 64 + kp * 16, w1d, a);
            *(float4*)&psum[n][kp][c0] =
                make_float4(hadd2(a[0]), hadd2(a[1]), hadd2(a[2]), hadd2(a[3]));
        }
        __syncthreads();
#pragma unroll
        for (int n = 0; n < 8; n++) {
            float hv = psum[n][0][t] + psum[n][1][t] + psum[n][2][t] + psum[n][3][t];
            g_hid[(n0 + n) * 256 + t] = fmaxf(hv + b1t, 0.f);
        }
        if (t < 128 && pn < ngrp) ((float4*)xs[it ^ 1])[t] = nx;
        __syncthreads();
    }
}

// ---------------- FFN GEMM2: psum form (R8), warp-per-node LN ----------------
__global__ __launch_bounds__(256, 2) void k_ffn2(const float* __restrict__ w2,
                                                 const float* __restrict__ b2,
                                                 const float* __restrict__ lg,
                                                 const float* __restrict__ lb,
                                                 float* __restrict__ out) {
    __shared__ __align__(16) float xs[512];
    __shared__ __align__(16) float hs[2048];
    __shared__ __align__(16) float psum[8][16][64];   // 32 kB
    int t = threadIdx.x;
    int kp = t >> 4, cp = t & 15;
    int c0 = 4 * cp;
    int wnode = t >> 5, l = t & 31;
    u64 w2d[4][8];
#pragma unroll
    for (int ch = 0; ch < 4; ch++)
#pragma unroll
        for (int j = 0; j < 8; j++)
            w2d[ch][j] = pack2(w2[(kp * 16 + 2 * j) * 64 + c0 + ch],
                               w2[(kp * 16 + 2 * j + 1) * 64 + c0 + ch]);
    float b2A = b2[l], b2B = b2[l + 32];
    float gA = lg[l], gB = lg[l + 32], bA = lb[l], bB = lb[l + 32];

    const int ngrp = N_NODES / 8;
    for (int p = blockIdx.x; p < ngrp; p += gridDim.x) {
        int n0 = 8 * p;
        if (t < 128) ((float4*)xs)[t] = ((const float4*)(g_x1 + n0 * 64))[t];
        ((float4*)hs)[t]       = ((const float4*)(g_hid + n0 * 256))[t];
        ((float4*)hs)[t + 256] = ((const float4*)(g_hid + n0 * 256))[t + 256];
        __syncthreads();
#pragma unroll
        for (int n = 0; n < 8; n++) {
            u64 a[4] = {0ull, 0ull, 0ull, 0ull};
            gemm16x4(hs + n * 256 + kp * 16, w2d, a);
            *(float4*)&psum[n][kp][c0] =
                make_float4(hadd2(a[0]), hadd2(a[1]), hadd2(a[2]), hadd2(a[3]));
        }
        __syncthreads();
        {
            float oA = b2A, oB = b2B;
#pragma unroll
            for (int q = 0; q < 16; q++) {
                oA += psum[wnode][q][l];
                oB += psum[wnode][q][l + 32];
            }
            float vA = xs[wnode * 64 + l] + oA;
            float vB = xs[wnode * 64 + l + 32] + oB;
            float sum = vA + vB, sq = vA * vA + vB * vB;
#pragma unroll
            for (int o = 16; o; o >>= 1) {
                sum += __shfl_xor_sync(0xffffffffu, sum, o);
                sq  += __shfl_xor_sync(0xffffffffu, sq, o);
            }
            float mean = sum * (1.f / 64.f);
            float var = sq * (1.f / 64.f) - mean * mean;
            float rstd = rsqrtf(var + LN_EPS);
            out[(n0 + wnode) * 64 + l]      = (vA - mean) * rstd * gA + bA;
            out[(n0 + wnode) * 64 + l + 32] = (vB - mean) * rstd * gB + bB;
        }
        __syncthreads();
    }
}

extern "C" void kernel_launch(void* const* d_in, const int* in_sizes, int n_in,
                              void* d_out, int out_size) {
    const float* x      = (const float*)d_in[0];
    const void*  ei     = d_in[1];
    const float* attn_w = (const float*)d_in[2];
    const float* attn_b = (const float*)d_in[3];
    const float* w1     = (const float*)d_in[4];
    const float* b1     = (const float*)d_in[5];
    const float* w2     = (const float*)d_in[6];
    const float* b2     = (const float*)d_in[7];
    const float* ln1_g  = (const float*)d_in[8];
    const float* ln1_b  = (const float*)d_in[9];
    const float* ln2_g  = (const float*)d_in[10];
    const float* ln2_b  = (const float*)d_in[11];
    float* out = (float*)d_out;

    k_qkv<<<296, 192>>>(x, attn_w, attn_b, ei);
    k_scatter<<<N_EDGES / 256, 256>>>(ei);
    k_gather<<<N_NODES / 32, 256>>>(x, ln1_g, ln1_b);
    k_ffn1<<<296, 256>>>(w1, b1);
    k_ffn2<<<296, 256>>>(w2, b2, ln2_g, ln2_b, out);
}

// round 11
// speedup vs baseline: 2.9447x; 1.7449x over previous
#include <cuda_runtime.h>
#include <cuda_bf16.h>

#define N_NODES 100000
#define N_EDGES 1600000
#define EMBED 64
#define HEADS 8
#define FFN_DIM 256
#define LN_EPS 1e-5f
#define CAP 128

typedef unsigned long long u64;

// ---------------- tf32 mma.sync helpers ----------------
__device__ __forceinline__ void mma8(float* acc, const unsigned* a, const unsigned* b) {
    asm volatile("mma.sync.aligned.m16n8k8.row.col.f32.tf32.tf32.f32 "
                 "{%0,%1,%2,%3},{%4,%5,%6,%7},{%8,%9},{%0,%1,%2,%3};"
                 : "+f"(acc[0]), "+f"(acc[1]), "+f"(acc[2]), "+f"(acc[3])
                 : "r"(a[0]), "r"(a[1]), "r"(a[2]), "r"(a[3]), "r"(b[0]), "r"(b[1]));
}
// A fragment from padded smem: base = &tile[(row0+gid)*S + k0 + tig]
__device__ __forceinline__ void lda(unsigned a[4], const float* base, int S) {
    a[0] = __float_as_uint(base[0]);
    a[1] = __float_as_uint(base[8 * S]);
    a[2] = __float_as_uint(base[4]);
    a[3] = __float_as_uint(base[8 * S + 4]);
}

// ---------------- scratch ----------------
__device__ float g_q[N_NODES * EMBED];
__device__ float g_k[N_NODES * EMBED];
__device__ float g_v[N_NODES * EMBED];
__device__ float g_x1[N_NODES * EMBED];
__device__ float g_hid[N_NODES * FFN_DIM];
__device__ int   g_cnt[N_NODES];
__device__ int   g_bcol[N_NODES * CAP];
__device__ int   g_is64;

// ---------------- QKV: tf32 mma, 32-node tiles, double-buffered ----------------
// warp wp: channels [wp*24, wp*24+24) of 192; B-frags in regs (k=64)
__global__ __launch_bounds__(256, 2) void k_qkv(const float* __restrict__ x,
                                                const float* __restrict__ w,
                                                const float* __restrict__ b,
                                                const void* __restrict__ ei) {
    int t = threadIdx.x;
    for (int gi = blockIdx.x * 256 + t; gi < N_NODES; gi += gridDim.x * 256) g_cnt[gi] = 0;
    if (blockIdx.x == 0 && t == 0) {
        const unsigned* wr = (const unsigned*)ei;
        int is64 = 1;
        for (int q = 1; q < 256; q += 2) if (wr[q] != 0u) { is64 = 0; break; }
        g_is64 = is64;
    }
    __shared__ __align__(16) float xs[2][32 * 68];
    int wp = t >> 5, l = t & 31, gid = l >> 2, tig = l & 3;
    int nb = wp * 24;
    unsigned bfr[3][8][2];
#pragma unroll
    for (int nt = 0; nt < 3; nt++)
#pragma unroll
        for (int ks = 0; ks < 8; ks++) {
            bfr[nt][ks][0] = __float_as_uint(w[(ks * 8 + tig) * 192 + nb + nt * 8 + gid]);
            bfr[nt][ks][1] = __float_as_uint(w[(ks * 8 + tig + 4) * 192 + nb + nt * 8 + gid]);
        }
    float* dstp[3]; int doff[3]; float2 bias[3];
#pragma unroll
    for (int nt = 0; nt < 3; nt++) {
        int ch0 = nb + nt * 8 + 2 * tig;
        int h = ch0 / 24, r = ch0 % 24;
        dstp[nt] = (r < 8) ? g_q : (r < 16 ? g_k : g_v);
        doff[nt] = h * 8 + (r & 7);
        bias[nt] = make_float2(b[ch0], b[ch0 + 1]);
    }

    const int ngrp = N_NODES / 32;   // 3125
    const int stride = gridDim.x;
    int p = blockIdx.x;
    if (p < ngrp) {
#pragma unroll
        for (int j = 0; j < 2; j++) {
            int i = t + j * 256;
            float4 v = ((const float4*)(x + p * 2048))[i];
            *(float4*)&xs[0][(i >> 4) * 68 + (i & 15) * 4] = v;
        }
    }
    __syncthreads();
    for (int it = 0; p < ngrp; p += stride, it ^= 1) {
        int pn = p + stride;
        float4 nx0, nx1;
        if (pn < ngrp) {
            nx0 = ((const float4*)(x + pn * 2048))[t];
            nx1 = ((const float4*)(x + pn * 2048))[t + 256];
        }
        int n0 = p * 32;
#pragma unroll
        for (int mh = 0; mh < 2; mh++) {
            float acc[3][4] = {{0.f,0.f,0.f,0.f},{0.f,0.f,0.f,0.f},{0.f,0.f,0.f,0.f}};
#pragma unroll
            for (int ks = 0; ks < 8; ks++) {
                unsigned a[4];
                lda(a, &xs[it][(mh * 16 + gid) * 68 + ks * 8 + tig], 68);
                mma8(acc[0], a, bfr[0][ks]);
                mma8(acc[1], a, bfr[1][ks]);
                mma8(acc[2], a, bfr[2][ks]);
            }
            int na = n0 + mh * 16 + gid;
#pragma unroll
            for (int nt = 0; nt < 3; nt++) {
                *(float2*)&dstp[nt][na * 64 + doff[nt]] =
                    make_float2(acc[nt][0] + bias[nt].x, acc[nt][1] + bias[nt].y);
                *(float2*)&dstp[nt][(na + 8) * 64 + doff[nt]] =
                    make_float2(acc[nt][2] + bias[nt].x, acc[nt][3] + bias[nt].y);
            }
        }
        if (pn < ngrp) {
            *(float4*)&xs[it ^ 1][(t >> 4) * 68 + (t & 15) * 4] = nx0;
            int i = t + 256;
            *(float4*)&xs[it ^ 1][(i >> 4) * 68 + (i & 15) * 4] = nx1;
        }
        __syncthreads();
    }
}

// ---------------- bucket scatter ----------------
__global__ void k_scatter(const void* __restrict__ ei_raw) {
    int e = blockIdx.x * blockDim.x + threadIdx.x;
    if (e >= N_EDGES) return;
    int r, c;
    if (g_is64) {
        const long long* ei = (const long long*)ei_raw;
        r = (int)ei[e]; c = (int)ei[N_EDGES + e];
    } else {
        const int* ei = (const int*)ei_raw;
        r = ei[e]; c = ei[N_EDGES + e];
    }
    int slot = atomicAdd(&g_cnt[r], 1);
    if (slot < CAP) g_bcol[r * CAP + slot] = c;
}

// ---------------- gather attention + residual + LN1 ----------------
__global__ __launch_bounds__(256) void k_gather(const float* __restrict__ x,
                                                const float* __restrict__ lg,
                                                const float* __restrict__ lb) {
    int t = threadIdx.x;
    int n = blockIdx.x * 32 + (t >> 3);
    int h = t & 7;
    const int base = n * 64 + h * 8;
    const float4* qp = (const float4*)(g_q + base);
    float4 q0 = qp[0], q1 = qp[1];

    int deg = g_cnt[n];
    if (deg > CAP) deg = CAP;

    float den = 0.f;
    float4 a0 = make_float4(0.f, 0.f, 0.f, 0.f);
    float4 a1 = make_float4(0.f, 0.f, 0.f, 0.f);

    const int* bp = g_bcol + n * CAP;
    int cnext = (deg > 0) ? bp[0] : 0;
    for (int s = 0; s < deg; s++) {
        int c = cnext;
        cnext = (s + 1 < deg) ? bp[s + 1] : 0;
        const float4* kp = (const float4*)(g_k + c * 64 + h * 8);
        const float4* vp = (const float4*)(g_v + c * 64 + h * 8);
        float4 k0 = kp[0], k1 = kp[1];
        float4 v0 = vp[0], v1 = vp[1];
        float dot = q0.x * k0.x + q0.y * k0.y + q0.z * k0.z + q0.w * k0.w
                  + q1.x * k1.x + q1.y * k1.y + q1.z * k1.z + q1.w * k1.w;
        float ew = __expf(dot * 0.125f);
        den += ew;
        a0.x += ew * v0.x; a0.y += ew * v0.y; a0.z += ew * v0.z; a0.w += ew * v0.w;
        a1.x += ew * v1.x; a1.y += ew * v1.y; a1.z += ew * v1.z; a1.w += ew * v1.w;
    }
    float inv = (den > 0.f) ? (1.f / den) : 0.f;

    const float4* xp = (const float4*)(x + base);
    float4 x0 = xp[0], x1 = xp[1];
    float s_[8];
    s_[0] = x0.x + a0.x * inv; s_[1] = x0.y + a0.y * inv;
    s_[2] = x0.z + a0.z * inv; s_[3] = x0.w + a0.w * inv;
    s_[4] = x1.x + a1.x * inv; s_[5] = x1.y + a1.y * inv;
    s_[6] = x1.z + a1.z * inv; s_[7] = x1.w + a1.w * inv;
    float sum = 0.f, sq = 0.f;
#pragma unroll
    for (int j = 0; j < 8; j++) { sum += s_[j]; sq += s_[j] * s_[j]; }
#pragma unroll
    for (int o = 4; o; o >>= 1) {
        sum += __shfl_xor_sync(0xffffffffu, sum, o);
        sq  += __shfl_xor_sync(0xffffffffu, sq, o);
    }
    float mean = sum * (1.f / 64.f);
    float var = sq * (1.f / 64.f) - mean * mean;
    float rstd = rsqrtf(var + LN_EPS);
    float4 y0, y1;
    int c0 = h * 8;
    y0.x = (s_[0] - mean) * rstd * lg[c0 + 0] + lb[c0 + 0];
    y0.y = (s_[1] - mean) * rstd * lg[c0 + 1] + lb[c0 + 1];
    y0.z = (s_[2] - mean) * rstd * lg[c0 + 2] + lb[c0 + 2];
    y0.w = (s_[3] - mean) * rstd * lg[c0 + 3] + lb[c0 + 3];
    y1.x = (s_[4] - mean) * rstd * lg[c0 + 4] + lb[c0 + 4];
    y1.y = (s_[5] - mean) * rstd * lg[c0 + 5] + lb[c0 + 5];
    y1.z = (s_[6] - mean) * rstd * lg[c0 + 6] + lb[c0 + 6];
    y1.w = (s_[7] - mean) * rstd * lg[c0 + 7] + lb[c0 + 7];
    float4* op = (float4*)(g_x1 + base);
    op[0] = y0; op[1] = y1;
}

// ---------------- FFN GEMM1: tf32 mma, 32-node tiles, n32/warp ----------------
__global__ __launch_bounds__(256, 2) void k_ffn1(const float* __restrict__ w1,
                                                 const float* __restrict__ b1) {
    __shared__ __align__(16) float xs[2][32 * 68];
    int t = threadIdx.x;
    int wp = t >> 5, l = t & 31, gid = l >> 2, tig = l & 3;
    int nb = wp * 32;
    unsigned bfr[4][8][2];
#pragma unroll
    for (int nt = 0; nt < 4; nt++)
#pragma unroll
        for (int ks = 0; ks < 8; ks++) {
            bfr[nt][ks][0] = __float_as_uint(w1[(ks * 8 + tig) * 256 + nb + nt * 8 + gid]);
            bfr[nt][ks][1] = __float_as_uint(w1[(ks * 8 + tig + 4) * 256 + nb + nt * 8 + gid]);
        }
    float2 bias[4];
#pragma unroll
    for (int nt = 0; nt < 4; nt++) {
        int ch0 = nb + nt * 8 + 2 * tig;
        bias[nt] = make_float2(b1[ch0], b1[ch0 + 1]);
    }

    const int ngrp = N_NODES / 32;
    const int stride = gridDim.x;
    int p = blockIdx.x;
    if (p < ngrp) {
#pragma unroll
        for (int j = 0; j < 2; j++) {
            int i = t + j * 256;
            float4 v = ((const float4*)(g_x1 + p * 2048))[i];
            *(float4*)&xs[0][(i >> 4) * 68 + (i & 15) * 4] = v;
        }
    }
    __syncthreads();
    for (int it = 0; p < ngrp; p += stride, it ^= 1) {
        int pn = p + stride;
        float4 nx0, nx1;
        if (pn < ngrp) {
            nx0 = ((const float4*)(g_x1 + pn * 2048))[t];
            nx1 = ((const float4*)(g_x1 + pn * 2048))[t + 256];
        }
        int n0 = p * 32;
#pragma unroll
        for (int mh = 0; mh < 2; mh++) {
            float acc[4][4] = {{0.f,0.f,0.f,0.f},{0.f,0.f,0.f,0.f},
                               {0.f,0.f,0.f,0.f},{0.f,0.f,0.f,0.f}};
#pragma unroll
            for (int ks = 0; ks < 8; ks++) {
                unsigned a[4];
                lda(a, &xs[it][(mh * 16 + gid) * 68 + ks * 8 + tig], 68);
                mma8(acc[0], a, bfr[0][ks]);
                mma8(acc[1], a, bfr[1][ks]);
                mma8(acc[2], a, bfr[2][ks]);
                mma8(acc[3], a, bfr[3][ks]);
            }
            int na = n0 + mh * 16 + gid;
#pragma unroll
            for (int nt = 0; nt < 4; nt++) {
                int ch0 = nb + nt * 8 + 2 * tig;
                *(float2*)&g_hid[na * 256 + ch0] =
                    make_float2(fmaxf(acc[nt][0] + bias[nt].x, 0.f),
                                fmaxf(acc[nt][1] + bias[nt].y, 0.f));
                *(float2*)&g_hid[(na + 8) * 256 + ch0] =
                    make_float2(fmaxf(acc[nt][2] + bias[nt].x, 0.f),
                                fmaxf(acc[nt][3] + bias[nt].y, 0.f));
            }
        }
        if (pn < ngrp) {
            *(float4*)&xs[it ^ 1][(t >> 4) * 68 + (t & 15) * 4] = nx0;
            int i = t + 256;
            *(float4*)&xs[it ^ 1][(i >> 4) * 68 + (i & 15) * 4] = nx1;
        }
        __syncthreads();
    }
}

// ---------------- FFN GEMM2: tf32 mma, 16-node tiles, n16 x k128 per warp + LN2 ----------------
__global__ __launch_bounds__(256, 2) void k_ffn2(const float* __restrict__ w2,
                                                 const float* __restrict__ b2,
                                                 const float* __restrict__ lg,
                                                 const float* __restrict__ lb,
                                                 float* __restrict__ out) {
    __shared__ __align__(16) float hs[16 * 260];       // 16.6 kB
    __shared__ __align__(16) float xr[16 * 68];        // 4.4 kB
    __shared__ __align__(16) float osum[2][16 * 68];   // 8.7 kB
    int t = threadIdx.x;
    int wp = t >> 5, l = t & 31, gid = l >> 2, tig = l & 3;
    int kw = wp >> 2, nw2 = wp & 3;
    unsigned bfr[2][16][2];
#pragma unroll
    for (int nt = 0; nt < 2; nt++)
#pragma unroll
        for (int ks = 0; ks < 16; ks++) {
            int kk = kw * 128 + ks * 8;
            bfr[nt][ks][0] = __float_as_uint(w2[(kk + tig) * 64 + nw2 * 16 + nt * 8 + gid]);
            bfr[nt][ks][1] = __float_as_uint(w2[(kk + tig + 4) * 64 + nw2 * 16 + nt * 8 + gid]);
        }
    // LN epilogue params (thread t<128: node = t>>3, oh = t&7)
    int oh = t & 7;
    float4 lg0 = *(const float4*)&lg[oh * 8],  lg1 = *(const float4*)&lg[oh * 8 + 4];
    float4 lb0 = *(const float4*)&lb[oh * 8],  lb1 = *(const float4*)&lb[oh * 8 + 4];
    float4 b20 = *(const float4*)&b2[oh * 8],  b21 = *(const float4*)&b2[oh * 8 + 4];

    const int ngrp = N_NODES / 16;   // 6250
    for (int p = blockIdx.x; p < ngrp; p += gridDim.x) {
        int n0 = p * 16;
#pragma unroll
        for (int j = 0; j < 4; j++) {
            int i = t + j * 256;
            float4 v = ((const float4*)(g_hid + n0 * 256))[i];
            *(float4*)&hs[(i >> 6) * 260 + (i & 63) * 4] = v;
        }
        {
            float4 v = ((const float4*)(g_x1 + n0 * 64))[t];
            *(float4*)&xr[(t >> 4) * 68 + (t & 15) * 4] = v;
        }
        __syncthreads();
        {
            float acc[2][4] = {{0.f,0.f,0.f,0.f},{0.f,0.f,0.f,0.f}};
#pragma unroll
            for (int ks = 0; ks < 16; ks++) {
                unsigned a[4];
                lda(a, &hs[gid * 260 + kw * 128 + ks * 8 + tig], 260);
                mma8(acc[0], a, bfr[0][ks]);
                mma8(acc[1], a, bfr[1][ks]);
            }
#pragma unroll
            for (int nt = 0; nt < 2; nt++) {
                int ch0 = nw2 * 16 + nt * 8 + 2 * tig;
                *(float2*)&osum[kw][gid * 68 + ch0]       = make_float2(acc[nt][0], acc[nt][1]);
                *(float2*)&osum[kw][(gid + 8) * 68 + ch0] = make_float2(acc[nt][2], acc[nt][3]);
            }
        }
        __syncthreads();
        if (t < 128) {
            int node = t >> 3;
            int bi = node * 68 + oh * 8;
            float s[8];
            s[0] = xr[bi+0] + osum[0][bi+0] + osum[1][bi+0] + b20.x;
            s[1] = xr[bi+1] + osum[0][bi+1] + osum[1][bi+1] + b20.y;
            s[2] = xr[bi+2] + osum[0][bi+2] + osum[1][bi+2] + b20.z;
            s[3] = xr[bi+3] + osum[0][bi+3] + osum[1][bi+3] + b20.w;
            s[4] = xr[bi+4] + osum[0][bi+4] + osum[1][bi+4] + b21.x;
            s[5] = xr[bi+5] + osum[0][bi+5] + osum[1][bi+5] + b21.y;
            s[6] = xr[bi+6] + osum[0][bi+6] + osum[1][bi+6] + b21.z;
            s[7] = xr[bi+7] + osum[0][bi+7] + osum[1][bi+7] + b21.w;
            float sum = 0.f, sq = 0.f;
#pragma unroll
            for (int j = 0; j < 8; j++) { sum += s[j]; sq += s[j] * s[j]; }
#pragma unroll
            for (int o = 4; o; o >>= 1) {
                sum += __shfl_xor_sync(0xffffffffu, sum, o);
                sq  += __shfl_xor_sync(0xffffffffu, sq, o);
            }
            float mean = sum * (1.f / 64.f);
            float var = sq * (1.f / 64.f) - mean * mean;
            float rstd = rsqrtf(var + LN_EPS);
            float4 o0, o1;
            o0.x = (s[0] - mean) * rstd * lg0.x + lb0.x;
            o0.y = (s[1] - mean) * rstd * lg0.y + lb0.y;
            o0.z = (s[2] - mean) * rstd * lg0.z + lb0.z;
            o0.w = (s[3] - mean) * rstd * lg0.w + lb0.w;
            o1.x = (s[4] - mean) * rstd * lg1.x + lb1.x;
            o1.y = (s[5] - mean) * rstd * lg1.y + lb1.y;
            o1.z = (s[6] - mean) * rstd * lg1.z + lb1.z;
            o1.w = (s[7] - mean) * rstd * lg1.w + lb1.w;
            *(float4*)&out[(n0 + node) * 64 + oh * 8]     = o0;
            *(float4*)&out[(n0 + node) * 64 + oh * 8 + 4] = o1;
        }
        __syncthreads();
    }
}

extern "C" void kernel_launch(void* const* d_in, const int* in_sizes, int n_in,
                              void* d_out, int out_size) {
    const float* x      = (const float*)d_in[0];
    const void*  ei     = d_in[1];
    const float* attn_w = (const float*)d_in[2];
    const float* attn_b = (const float*)d_in[3];
    const float* w1     = (const float*)d_in[4];
    const float* b1     = (const float*)d_in[5];
    const float* w2     = (const float*)d_in[6];
    const float* b2     = (const float*)d_in[7];
    const float* ln1_g  = (const float*)d_in[8];
    const float* ln1_b  = (const float*)d_in[9];
    const float* ln2_g  = (const float*)d_in[10];
    const float* ln2_b  = (const float*)d_in[11];
    float* out = (float*)d_out;

    k_qkv<<<296, 256>>>(x, attn_w, attn_b, ei);
    k_scatter<<<N_EDGES / 256, 256>>>(ei);
    k_gather<<<N_NODES / 32, 256>>>(x, ln1_g, ln1_b);
    k_ffn1<<<296, 256>>>(w1, b1);
    k_ffn2<<<296, 256>>>(w2, b2, ln2_g, ln2_b, out);
}

// round 12
// speedup vs baseline: 3.7286x; 1.2662x over previous
#include <cuda_runtime.h>
#include <cuda_bf16.h>
#include <cuda_fp16.h>

#define N_NODES 100000
#define N_EDGES 1600000
#define EMBED 64
#define HEADS 8
#define FFN_DIM 256
#define LN_EPS 1e-5f
#define CAP 128

typedef unsigned long long u64;

// ---------------- tf32 mma.sync helpers ----------------
__device__ __forceinline__ void mma8(float* acc, const unsigned* a, const unsigned* b) {
    asm volatile("mma.sync.aligned.m16n8k8.row.col.f32.tf32.tf32.f32 "
                 "{%0,%1,%2,%3},{%4,%5,%6,%7},{%8,%9},{%0,%1,%2,%3};"
                 : "+f"(acc[0]), "+f"(acc[1]), "+f"(acc[2]), "+f"(acc[3])
                 : "r"(a[0]), "r"(a[1]), "r"(a[2]), "r"(a[3]), "r"(b[0]), "r"(b[1]));
}
__device__ __forceinline__ void mma16h(float* acc, const unsigned* a, const unsigned* b) {
    asm volatile("mma.sync.aligned.m16n8k16.row.col.f32.f16.f16.f32 "
                 "{%0,%1,%2,%3},{%4,%5,%6,%7},{%8,%9},{%0,%1,%2,%3};"
                 : "+f"(acc[0]), "+f"(acc[1]), "+f"(acc[2]), "+f"(acc[3])
                 : "r"(a[0]), "r"(a[1]), "r"(a[2]), "r"(a[3]), "r"(b[0]), "r"(b[1]));
}
// tf32 A fragment from padded fp32 smem
__device__ __forceinline__ void lda(unsigned a[4], const float* base, int S) {
    a[0] = __float_as_uint(base[0]);
    a[1] = __float_as_uint(base[8 * S]);
    a[2] = __float_as_uint(base[4]);
    a[3] = __float_as_uint(base[8 * S + 4]);
}

// ---------------- scratch ----------------
__device__ float  g_q[N_NODES * EMBED];
__device__ __half g_kh[N_NODES * EMBED];
__device__ __half g_vh[N_NODES * EMBED];
__device__ float  g_x1[N_NODES * EMBED];
__device__ __half g_hidh[N_NODES * FFN_DIM];
__device__ int    g_cnt[N_NODES];
__device__ int    g_bcol[N_NODES * CAP];
__device__ int    g_is64;

// ---------------- QKV: tf32 mma; q fp32, k/v fp16 ----------------
__global__ __launch_bounds__(256, 2) void k_qkv(const float* __restrict__ x,
                                                const float* __restrict__ w,
                                                const float* __restrict__ b,
                                                const void* __restrict__ ei) {
    int t = threadIdx.x;
    for (int gi = blockIdx.x * 256 + t; gi < N_NODES; gi += gridDim.x * 256) g_cnt[gi] = 0;
    if (blockIdx.x == 0 && t == 0) {
        const unsigned* wr = (const unsigned*)ei;
        int is64 = 1;
        for (int q = 1; q < 256; q += 2) if (wr[q] != 0u) { is64 = 0; break; }
        g_is64 = is64;
    }
    __shared__ __align__(16) float xs[2][32 * 68];
    int wp = t >> 5, l = t & 31, gid = l >> 2, tig = l & 3;
    int nb = wp * 24;
    unsigned bfr[3][8][2];
#pragma unroll
    for (int nt = 0; nt < 3; nt++)
#pragma unroll
        for (int ks = 0; ks < 8; ks++) {
            bfr[nt][ks][0] = __float_as_uint(w[(ks * 8 + tig) * 192 + nb + nt * 8 + gid]);
            bfr[nt][ks][1] = __float_as_uint(w[(ks * 8 + tig + 4) * 192 + nb + nt * 8 + gid]);
        }
    int seg[3], doff[3]; float2 bias[3];
#pragma unroll
    for (int nt = 0; nt < 3; nt++) {
        int ch0 = nb + nt * 8 + 2 * tig;
        int h = ch0 / 24, r = ch0 % 24;
        seg[nt] = (r < 8) ? 0 : ((r < 16) ? 1 : 2);
        doff[nt] = h * 8 + (r & 7);
        bias[nt] = make_float2(b[ch0], b[ch0 + 1]);
    }

    const int ngrp = N_NODES / 32;
    const int stride = gridDim.x;
    int p = blockIdx.x;
    if (p < ngrp) {
#pragma unroll
        for (int j = 0; j < 2; j++) {
            int i = t + j * 256;
            float4 v = ((const float4*)(x + p * 2048))[i];
            *(float4*)&xs[0][(i >> 4) * 68 + (i & 15) * 4] = v;
        }
    }
    __syncthreads();
    for (int it = 0; p < ngrp; p += stride, it ^= 1) {
        int pn = p + stride;
        float4 nx0, nx1;
        if (pn < ngrp) {
            nx0 = ((const float4*)(x + pn * 2048))[t];
            nx1 = ((const float4*)(x + pn * 2048))[t + 256];
        }
        int n0 = p * 32;
#pragma unroll
        for (int mh = 0; mh < 2; mh++) {
            float acc[3][4] = {{0.f,0.f,0.f,0.f},{0.f,0.f,0.f,0.f},{0.f,0.f,0.f,0.f}};
#pragma unroll
            for (int ks = 0; ks < 8; ks++) {
                unsigned a[4];
                lda(a, &xs[it][(mh * 16 + gid) * 68 + ks * 8 + tig], 68);
                mma8(acc[0], a, bfr[0][ks]);
                mma8(acc[1], a, bfr[1][ks]);
                mma8(acc[2], a, bfr[2][ks]);
            }
            int na = n0 + mh * 16 + gid;
#pragma unroll
            for (int nt = 0; nt < 3; nt++) {
                float vx0 = acc[nt][0] + bias[nt].x, vy0 = acc[nt][1] + bias[nt].y;
                float vx1 = acc[nt][2] + bias[nt].x, vy1 = acc[nt][3] + bias[nt].y;
                if (seg[nt] == 0) {
                    *(float2*)&g_q[na * 64 + doff[nt]]       = make_float2(vx0, vy0);
                    *(float2*)&g_q[(na + 8) * 64 + doff[nt]] = make_float2(vx1, vy1);
                } else {
                    __half* base = (seg[nt] == 1) ? g_kh : g_vh;
                    *(__half2*)&base[na * 64 + doff[nt]]       = __floats2half2_rn(vx0, vy0);
                    *(__half2*)&base[(na + 8) * 64 + doff[nt]] = __floats2half2_rn(vx1, vy1);
                }
            }
        }
        if (pn < ngrp) {
            *(float4*)&xs[it ^ 1][(t >> 4) * 68 + (t & 15) * 4] = nx0;
            int i = t + 256;
            *(float4*)&xs[it ^ 1][(i >> 4) * 68 + (i & 15) * 4] = nx1;
        }
        __syncthreads();
    }
}

// ---------------- bucket scatter ----------------
__global__ void k_scatter(const void* __restrict__ ei_raw) {
    int e = blockIdx.x * blockDim.x + threadIdx.x;
    if (e >= N_EDGES) return;
    int r, c;
    if (g_is64) {
        const long long* ei = (const long long*)ei_raw;
        r = (int)ei[e]; c = (int)ei[N_EDGES + e];
    } else {
        const int* ei = (const int*)ei_raw;
        r = ei[e]; c = ei[N_EDGES + e];
    }
    int slot = atomicAdd(&g_cnt[r], 1);
    if (slot < CAP) g_bcol[r * CAP + slot] = c;
}

// ---------------- gather attention (fp16 k/v) + residual + LN1 ----------------
__global__ __launch_bounds__(256) void k_gather(const float* __restrict__ x,
                                                const float* __restrict__ lg,
                                                const float* __restrict__ lb) {
    int t = threadIdx.x;
    int n = blockIdx.x * 32 + (t >> 3);
    int h = t & 7;
    const int base = n * 64 + h * 8;
    const float4* qp = (const float4*)(g_q + base);
    float4 q0 = qp[0], q1 = qp[1];

    int deg = g_cnt[n];
    if (deg > CAP) deg = CAP;

    float den = 0.f;
    float4 a0 = make_float4(0.f, 0.f, 0.f, 0.f);
    float4 a1 = make_float4(0.f, 0.f, 0.f, 0.f);

    const int* bp = g_bcol + n * CAP;
    int cnext = (deg > 0) ? bp[0] : 0;
    for (int s = 0; s < deg; s++) {
        int c = cnext;
        cnext = (s + 1 < deg) ? bp[s + 1] : 0;
        uint4 kr = *(const uint4*)(g_kh + c * 64 + h * 8);   // 8 halves = whole slice
        uint4 vr = *(const uint4*)(g_vh + c * 64 + h * 8);
        float2 k0 = __half22float2(*(__half2*)&kr.x);
        float2 k1 = __half22float2(*(__half2*)&kr.y);
        float2 k2 = __half22float2(*(__half2*)&kr.z);
        float2 k3 = __half22float2(*(__half2*)&kr.w);
        float dot = q0.x * k0.x + q0.y * k0.y + q0.z * k1.x + q0.w * k1.y
                  + q1.x * k2.x + q1.y * k2.y + q1.z * k3.x + q1.w * k3.y;
        float ew = __expf(dot * 0.125f);
        den += ew;
        float2 v0 = __half22float2(*(__half2*)&vr.x);
        float2 v1 = __half22float2(*(__half2*)&vr.y);
        float2 v2 = __half22float2(*(__half2*)&vr.z);
        float2 v3 = __half22float2(*(__half2*)&vr.w);
        a0.x += ew * v0.x; a0.y += ew * v0.y; a0.z += ew * v1.x; a0.w += ew * v1.y;
        a1.x += ew * v2.x; a1.y += ew * v2.y; a1.z += ew * v3.x; a1.w += ew * v3.y;
    }
    float inv = (den > 0.f) ? (1.f / den) : 0.f;

    const float4* xp = (const float4*)(x + base);
    float4 x0 = xp[0], x1 = xp[1];
    float s_[8];
    s_[0] = x0.x + a0.x * inv; s_[1] = x0.y + a0.y * inv;
    s_[2] = x0.z + a0.z * inv; s_[3] = x0.w + a0.w * inv;
    s_[4] = x1.x + a1.x * inv; s_[5] = x1.y + a1.y * inv;
    s_[6] = x1.z + a1.z * inv; s_[7] = x1.w + a1.w * inv;
    float sum = 0.f, sq = 0.f;
#pragma unroll
    for (int j = 0; j < 8; j++) { sum += s_[j]; sq += s_[j] * s_[j]; }
#pragma unroll
    for (int o = 4; o; o >>= 1) {
        sum += __shfl_xor_sync(0xffffffffu, sum, o);
        sq  += __shfl_xor_sync(0xffffffffu, sq, o);
    }
    float mean = sum * (1.f / 64.f);
    float var = sq * (1.f / 64.f) - mean * mean;
    float rstd = rsqrtf(var + LN_EPS);
    float4 y0, y1;
    int c0 = h * 8;
    y0.x = (s_[0] - mean) * rstd * lg[c0 + 0] + lb[c0 + 0];
    y0.y = (s_[1] - mean) * rstd * lg[c0 + 1] + lb[c0 + 1];
    y0.z = (s_[2] - mean) * rstd * lg[c0 + 2] + lb[c0 + 2];
    y0.w = (s_[3] - mean) * rstd * lg[c0 + 3] + lb[c0 + 3];
    y1.x = (s_[4] - mean) * rstd * lg[c0 + 4] + lb[c0 + 4];
    y1.y = (s_[5] - mean) * rstd * lg[c0 + 5] + lb[c0 + 5];
    y1.z = (s_[6] - mean) * rstd * lg[c0 + 6] + lb[c0 + 6];
    y1.w = (s_[7] - mean) * rstd * lg[c0 + 7] + lb[c0 + 7];
    float4* op = (float4*)(g_x1 + base);
    op[0] = y0; op[1] = y1;
}

// ---------------- FFN GEMM1: tf32 mma, fp16 hid out ----------------
__global__ __launch_bounds__(256, 2) void k_ffn1(const float* __restrict__ w1,
                                                 const float* __restrict__ b1) {
    __shared__ __align__(16) float xs[2][32 * 68];
    int t = threadIdx.x;
    int wp = t >> 5, l = t & 31, gid = l >> 2, tig = l & 3;
    int nb = wp * 32;
    unsigned bfr[4][8][2];
#pragma unroll
    for (int nt = 0; nt < 4; nt++)
#pragma unroll
        for (int ks = 0; ks < 8; ks++) {
            bfr[nt][ks][0] = __float_as_uint(w1[(ks * 8 + tig) * 256 + nb + nt * 8 + gid]);
            bfr[nt][ks][1] = __float_as_uint(w1[(ks * 8 + tig + 4) * 256 + nb + nt * 8 + gid]);
        }
    float2 bias[4];
#pragma unroll
    for (int nt = 0; nt < 4; nt++) {
        int ch0 = nb + nt * 8 + 2 * tig;
        bias[nt] = make_float2(b1[ch0], b1[ch0 + 1]);
    }

    const int ngrp = N_NODES / 32;
    const int stride = gridDim.x;
    int p = blockIdx.x;
    if (p < ngrp) {
#pragma unroll
        for (int j = 0; j < 2; j++) {
            int i = t + j * 256;
            float4 v = ((const float4*)(g_x1 + p * 2048))[i];
            *(float4*)&xs[0][(i >> 4) * 68 + (i & 15) * 4] = v;
        }
    }
    __syncthreads();
    for (int it = 0; p < ngrp; p += stride, it ^= 1) {
        int pn = p + stride;
        float4 nx0, nx1;
        if (pn < ngrp) {
            nx0 = ((const float4*)(g_x1 + pn * 2048))[t];
            nx1 = ((const float4*)(g_x1 + pn * 2048))[t + 256];
        }
        int n0 = p * 32;
#pragma unroll
        for (int mh = 0; mh < 2; mh++) {
            float acc[4][4] = {{0.f,0.f,0.f,0.f},{0.f,0.f,0.f,0.f},
                               {0.f,0.f,0.f,0.f},{0.f,0.f,0.f,0.f}};
#pragma unroll
            for (int ks = 0; ks < 8; ks++) {
                unsigned a[4];
                lda(a, &xs[it][(mh * 16 + gid) * 68 + ks * 8 + tig], 68);
                mma8(acc[0], a, bfr[0][ks]);
                mma8(acc[1], a, bfr[1][ks]);
                mma8(acc[2], a, bfr[2][ks]);
                mma8(acc[3], a, bfr[3][ks]);
            }
            int na = n0 + mh * 16 + gid;
#pragma unroll
            for (int nt = 0; nt < 4; nt++) {
                int ch0 = nb + nt * 8 + 2 * tig;
                *(__half2*)&g_hidh[na * 256 + ch0] =
                    __floats2half2_rn(fmaxf(acc[nt][0] + bias[nt].x, 0.f),
                                      fmaxf(acc[nt][1] + bias[nt].y, 0.f));
                *(__half2*)&g_hidh[(na + 8) * 256 + ch0] =
                    __floats2half2_rn(fmaxf(acc[nt][2] + bias[nt].x, 0.f),
                                      fmaxf(acc[nt][3] + bias[nt].y, 0.f));
            }
        }
        if (pn < ngrp) {
            *(float4*)&xs[it ^ 1][(t >> 4) * 68 + (t & 15) * 4] = nx0;
            int i = t + 256;
            *(float4*)&xs[it ^ 1][(i >> 4) * 68 + (i & 15) * 4] = nx1;
        }
        __syncthreads();
    }
}

// ---------------- FFN GEMM2: fp16 mma m16n8k16 + residual + LN2 ----------------
__global__ __launch_bounds__(256, 2) void k_ffn2(const float* __restrict__ w2,
                                                 const float* __restrict__ b2,
                                                 const float* __restrict__ lg,
                                                 const float* __restrict__ lb,
                                                 float* __restrict__ out) {
    __shared__ __align__(16) __half hs[16 * 264];      // 8.4 kB, stride 264 halves
    __shared__ __align__(16) float xr[16 * 68];
    __shared__ __align__(16) float osum[2][16 * 68];
    int t = threadIdx.x;
    int wp = t >> 5, l = t & 31, gid = l >> 2, tig = l & 3;
    int kw = wp >> 2, nw2 = wp & 3;
    unsigned bfr[2][8][2];
#pragma unroll
    for (int nt = 0; nt < 2; nt++)
#pragma unroll
        for (int ks = 0; ks < 8; ks++) {
            int kk = kw * 128 + ks * 16;
            int col = nw2 * 16 + nt * 8 + gid;
            __half2 h0 = __floats2half2_rn(w2[(kk + 2 * tig) * 64 + col],
                                           w2[(kk + 2 * tig + 1) * 64 + col]);
            __half2 h1 = __floats2half2_rn(w2[(kk + 2 * tig + 8) * 64 + col],
                                           w2[(kk + 2 * tig + 9) * 64 + col]);
            bfr[nt][ks][0] = *(unsigned*)&h0;
            bfr[nt][ks][1] = *(unsigned*)&h1;
        }
    int oh = t & 7;
    float4 lg0 = *(const float4*)&lg[oh * 8],  lg1 = *(const float4*)&lg[oh * 8 + 4];
    float4 lb0 = *(const float4*)&lb[oh * 8],  lb1 = *(const float4*)&lb[oh * 8 + 4];
    float4 b20 = *(const float4*)&b2[oh * 8],  b21 = *(const float4*)&b2[oh * 8 + 4];

    const int ngrp = N_NODES / 16;
    for (int p = blockIdx.x; p < ngrp; p += gridDim.x) {
        int n0 = p * 16;
#pragma unroll
        for (int j = 0; j < 2; j++) {
            int i = t + j * 256;   // 512 x uint4 = 16 nodes x 32 (8-half chunks)
            uint4 v = ((const uint4*)(g_hidh + n0 * 256))[i];
            *(uint4*)&hs[(i >> 5) * 264 + (i & 31) * 8] = v;
        }
        {
            float4 v = ((const float4*)(g_x1 + n0 * 64))[t];
            *(float4*)&xr[(t >> 4) * 68 + (t & 15) * 4] = v;
        }
        __syncthreads();
        {
            float acc[2][4] = {{0.f,0.f,0.f,0.f},{0.f,0.f,0.f,0.f}};
#pragma unroll
            for (int ks = 0; ks < 8; ks++) {
                int kk = kw * 128 + ks * 16;
                const __half* base = &hs[gid * 264 + kk + 2 * tig];
                unsigned a[4];
                a[0] = *(const unsigned*)(base);
                a[1] = *(const unsigned*)(base + 8 * 264);
                a[2] = *(const unsigned*)(base + 8);
                a[3] = *(const unsigned*)(base + 8 * 264 + 8);
                mma16h(acc[0], a, bfr[0][ks]);
                mma16h(acc[1], a, bfr[1][ks]);
            }
#pragma unroll
            for (int nt = 0; nt < 2; nt++) {
                int ch0 = nw2 * 16 + nt * 8 + 2 * tig;
                *(float2*)&osum[kw][gid * 68 + ch0]       = make_float2(acc[nt][0], acc[nt][1]);
                *(float2*)&osum[kw][(gid + 8) * 68 + ch0] = make_float2(acc[nt][2], acc[nt][3]);
            }
        }
        __syncthreads();
        if (t < 128) {
            int node = t >> 3;
            int bi = node * 68 + oh * 8;
            float s[8];
            s[0] = xr[bi+0] + osum[0][bi+0] + osum[1][bi+0] + b20.x;
            s[1] = xr[bi+1] + osum[0][bi+1] + osum[1][bi+1] + b20.y;
            s[2] = xr[bi+2] + osum[0][bi+2] + osum[1][bi+2] + b20.z;
            s[3] = xr[bi+3] + osum[0][bi+3] + osum[1][bi+3] + b20.w;
            s[4] = xr[bi+4] + osum[0][bi+4] + osum[1][bi+4] + b21.x;
            s[5] = xr[bi+5] + osum[0][bi+5] + osum[1][bi+5] + b21.y;
            s[6] = xr[bi+6] + osum[0][bi+6] + osum[1][bi+6] + b21.z;
            s[7] = xr[bi+7] + osum[0][bi+7] + osum[1][bi+7] + b21.w;
            float sum = 0.f, sq = 0.f;
#pragma unroll
            for (int j = 0; j < 8; j++) { sum += s[j]; sq += s[j] * s[j]; }
#pragma unroll
            for (int o = 4; o; o >>= 1) {
                sum += __shfl_xor_sync(0xffffffffu, sum, o);
                sq  += __shfl_xor_sync(0xffffffffu, sq, o);
            }
            float mean = sum * (1.f / 64.f);
            float var = sq * (1.f / 64.f) - mean * mean;
            float rstd = rsqrtf(var + LN_EPS);
            float4 o0, o1;
            o0.x = (s[0] - mean) * rstd * lg0.x + lb0.x;
            o0.y = (s[1] - mean) * rstd * lg0.y + lb0.y;
            o0.z = (s[2] - mean) * rstd * lg0.z + lb0.z;
            o0.w = (s[3] - mean) * rstd * lg0.w + lb0.w;
            o1.x = (s[4] - mean) * rstd * lg1.x + lb1.x;
            o1.y = (s[5] - mean) * rstd * lg1.y + lb1.y;
            o1.z = (s[6] - mean) * rstd * lg1.z + lb1.z;
            o1.w = (s[7] - mean) * rstd * lg1.w + lb1.w;
            *(float4*)&out[(n0 + node) * 64 + oh * 8]     = o0;
            *(float4*)&out[(n0 + node) * 64 + oh * 8 + 4] = o1;
        }
        __syncthreads();
    }
}

extern "C" void kernel_launch(void* const* d_in, const int* in_sizes, int n_in,
                              void* d_out, int out_size) {
    const float* x      = (const float*)d_in[0];
    const void*  ei     = d_in[1];
    const float* attn_w = (const float*)d_in[2];
    const float* attn_b = (const float*)d_in[3];
    const float* w1     = (const float*)d_in[4];
    const float* b1     = (const float*)d_in[5];
    const float* w2     = (const float*)d_in[6];
    const float* b2     = (const float*)d_in[7];
    const float* ln1_g  = (const float*)d_in[8];
    const float* ln1_b  = (const float*)d_in[9];
    const float* ln2_g  = (const float*)d_in[10];
    const float* ln2_b  = (const float*)d_in[11];
    float* out = (float*)d_out;

    k_qkv<<<296, 256>>>(x, attn_w, attn_b, ei);
    k_scatter<<<N_EDGES / 256, 256>>>(ei);
    k_gather<<<N_NODES / 32, 256>>>(x, ln1_g, ln1_b);
    k_ffn1<<<296, 256>>>(w1, b1);
    k_ffn2<<<296, 256>>>(w2, b2, ln2_g, ln2_b, out);
}

// round 13
// speedup vs baseline: 4.4215x; 1.1858x over previous
#include <cuda_runtime.h>
#include <cuda_bf16.h>
#include <cuda_fp16.h>

#define N_NODES 100000
#define N_EDGES 1600000
#define EMBED 64
#define HEADS 8
#define FFN_DIM 256
#define LN_EPS 1e-5f
#define CAP 128

typedef unsigned long long u64;

// ---------------- fp16 mma.sync m16n8k16 ----------------
__device__ __forceinline__ void mma16h(float* acc, const unsigned* a, const unsigned* b) {
    asm volatile("mma.sync.aligned.m16n8k16.row.col.f32.f16.f16.f32 "
                 "{%0,%1,%2,%3},{%4,%5,%6,%7},{%8,%9},{%0,%1,%2,%3};"
                 : "+f"(acc[0]), "+f"(acc[1]), "+f"(acc[2]), "+f"(acc[3])
                 : "r"(a[0]), "r"(a[1]), "r"(a[2]), "r"(a[3]), "r"(b[0]), "r"(b[1]));
}
// A fragment (m16n8k16) from padded fp16 smem, stride S halves
__device__ __forceinline__ void ldah(unsigned a[4], const __half* base, int S) {
    a[0] = *(const unsigned*)(base);
    a[1] = *(const unsigned*)(base + 8 * S);
    a[2] = *(const unsigned*)(base + 8);
    a[3] = *(const unsigned*)(base + 8 * S + 8);
}
// B fragment (m16n8k16, col-major) from global fp32 W[k][n], ld = row stride
__device__ __forceinline__ void ldbh(unsigned b[2], const float* W, int k0, int col, int ld) {
    __half2 h0 = __floats2half2_rn(W[(k0    ) * ld + col], W[(k0 + 1) * ld + col]);
    __half2 h1 = __floats2half2_rn(W[(k0 + 8) * ld + col], W[(k0 + 9) * ld + col]);
    b[0] = *(unsigned*)&h0;
    b[1] = *(unsigned*)&h1;
}

// ---------------- scratch ----------------
__device__ float  g_q[N_NODES * EMBED];
__device__ __half g_kh[N_NODES * EMBED];
__device__ __half g_vh[N_NODES * EMBED];
__device__ float  g_x1[N_NODES * EMBED];
__device__ int    g_cnt[N_NODES];
__device__ int    g_bcol[N_NODES * CAP];
__device__ int    g_is64;

// ---------------- QKV: fp16 mma; q fp32, k/v fp16 ----------------
__global__ __launch_bounds__(256, 2) void k_qkv(const float* __restrict__ x,
                                                const float* __restrict__ w,
                                                const float* __restrict__ b,
                                                const void* __restrict__ ei) {
    int t = threadIdx.x;
    for (int gi = blockIdx.x * 256 + t; gi < N_NODES; gi += gridDim.x * 256) g_cnt[gi] = 0;
    if (blockIdx.x == 0 && t == 0) {
        const unsigned* wr = (const unsigned*)ei;
        int is64 = 1;
        for (int q = 1; q < 256; q += 2) if (wr[q] != 0u) { is64 = 0; break; }
        g_is64 = is64;
    }
    __shared__ __align__(16) __half xh[2][32 * 72];
    int wp = t >> 5, l = t & 31, gid = l >> 2, tig = l & 3;
    int nb = wp * 24;
    unsigned bfr[3][4][2];
#pragma unroll
    for (int nt = 0; nt < 3; nt++)
#pragma unroll
        for (int ks = 0; ks < 4; ks++)
            ldbh(bfr[nt][ks], w, ks * 16 + 2 * tig, nb + nt * 8 + gid, 192);
    int seg[3], doff[3]; float2 bias[3];
#pragma unroll
    for (int nt = 0; nt < 3; nt++) {
        int ch0 = nb + nt * 8 + 2 * tig;
        int h = ch0 / 24, r = ch0 % 24;
        seg[nt] = (r < 8) ? 0 : ((r < 16) ? 1 : 2);
        doff[nt] = h * 8 + (r & 7);
        bias[nt] = make_float2(b[ch0], b[ch0 + 1]);
    }

    const int ngrp = N_NODES / 32;
    const int stride = gridDim.x;
    int p = blockIdx.x;
    if (p < ngrp) {
#pragma unroll
        for (int j = 0; j < 2; j++) {
            int i = t + j * 256;
            float4 v = ((const float4*)(x + p * 2048))[i];
            __half2 hA = __floats2half2_rn(v.x, v.y), hB = __floats2half2_rn(v.z, v.w);
            *(uint2*)&xh[0][(i >> 4) * 72 + (i & 15) * 4] =
                make_uint2(*(unsigned*)&hA, *(unsigned*)&hB);
        }
    }
    __syncthreads();
    for (int it = 0; p < ngrp; p += stride, it ^= 1) {
        int pn = p + stride;
        float4 nx0, nx1;
        if (pn < ngrp) {
            nx0 = ((const float4*)(x + pn * 2048))[t];
            nx1 = ((const float4*)(x + pn * 2048))[t + 256];
        }
        int n0 = p * 32;
#pragma unroll
        for (int mh = 0; mh < 2; mh++) {
            float acc[3][4] = {{0.f,0.f,0.f,0.f},{0.f,0.f,0.f,0.f},{0.f,0.f,0.f,0.f}};
#pragma unroll
            for (int ks = 0; ks < 4; ks++) {
                unsigned a[4];
                ldah(a, &xh[it][(mh * 16 + gid) * 72 + ks * 16 + 2 * tig], 72);
                mma16h(acc[0], a, bfr[0][ks]);
                mma16h(acc[1], a, bfr[1][ks]);
                mma16h(acc[2], a, bfr[2][ks]);
            }
            int na = n0 + mh * 16 + gid;
#pragma unroll
            for (int nt = 0; nt < 3; nt++) {
                float vx0 = acc[nt][0] + bias[nt].x, vy0 = acc[nt][1] + bias[nt].y;
                float vx1 = acc[nt][2] + bias[nt].x, vy1 = acc[nt][3] + bias[nt].y;
                if (seg[nt] == 0) {
                    *(float2*)&g_q[na * 64 + doff[nt]]       = make_float2(vx0, vy0);
                    *(float2*)&g_q[(na + 8) * 64 + doff[nt]] = make_float2(vx1, vy1);
                } else {
                    __half* base = (seg[nt] == 1) ? g_kh : g_vh;
                    *(__half2*)&base[na * 64 + doff[nt]]       = __floats2half2_rn(vx0, vy0);
                    *(__half2*)&base[(na + 8) * 64 + doff[nt]] = __floats2half2_rn(vx1, vy1);
                }
            }
        }
        if (pn < ngrp) {
            __half2 hA = __floats2half2_rn(nx0.x, nx0.y), hB = __floats2half2_rn(nx0.z, nx0.w);
            *(uint2*)&xh[it ^ 1][(t >> 4) * 72 + (t & 15) * 4] =
                make_uint2(*(unsigned*)&hA, *(unsigned*)&hB);
            int i = t + 256;
            hA = __floats2half2_rn(nx1.x, nx1.y); hB = __floats2half2_rn(nx1.z, nx1.w);
            *(uint2*)&xh[it ^ 1][(i >> 4) * 72 + (i & 15) * 4] =
                make_uint2(*(unsigned*)&hA, *(unsigned*)&hB);
        }
        __syncthreads();
    }
}

// ---------------- bucket scatter ----------------
__global__ void k_scatter(const void* __restrict__ ei_raw) {
    int e = blockIdx.x * blockDim.x + threadIdx.x;
    if (e >= N_EDGES) return;
    int r, c;
    if (g_is64) {
        const long long* ei = (const long long*)ei_raw;
        r = (int)ei[e]; c = (int)ei[N_EDGES + e];
    } else {
        const int* ei = (const int*)ei_raw;
        r = ei[e]; c = ei[N_EDGES + e];
    }
    int slot = atomicAdd(&g_cnt[r], 1);
    if (slot < CAP) g_bcol[r * CAP + slot] = c;
}

// ---------------- gather attention (fp16 k/v) + residual + LN1 ----------------
__global__ __launch_bounds__(256) void k_gather(const float* __restrict__ x,
                                                const float* __restrict__ lg,
                                                const float* __restrict__ lb) {
    int t = threadIdx.x;
    int n = blockIdx.x * 32 + (t >> 3);
    int h = t & 7;
    const int base = n * 64 + h * 8;
    const float4* qp = (const float4*)(g_q + base);
    float4 q0 = qp[0], q1 = qp[1];

    int deg = g_cnt[n];
    if (deg > CAP) deg = CAP;

    float den = 0.f;
    float4 a0 = make_float4(0.f, 0.f, 0.f, 0.f);
    float4 a1 = make_float4(0.f, 0.f, 0.f, 0.f);

    const int* bp = g_bcol + n * CAP;
    int cnext = (deg > 0) ? bp[0] : 0;
    for (int s = 0; s < deg; s++) {
        int c = cnext;
        cnext = (s + 1 < deg) ? bp[s + 1] : 0;
        uint4 kr = *(const uint4*)(g_kh + c * 64 + h * 8);
        uint4 vr = *(const uint4*)(g_vh + c * 64 + h * 8);
        float2 k0 = __half22float2(*(__half2*)&kr.x);
        float2 k1 = __half22float2(*(__half2*)&kr.y);
        float2 k2 = __half22float2(*(__half2*)&kr.z);
        float2 k3 = __half22float2(*(__half2*)&kr.w);
        float dot = q0.x * k0.x + q0.y * k0.y + q0.z * k1.x + q0.w * k1.y
                  + q1.x * k2.x + q1.y * k2.y + q1.z * k3.x + q1.w * k3.y;
        float ew = __expf(dot * 0.125f);
        den += ew;
        float2 v0 = __half22float2(*(__half2*)&vr.x);
        float2 v1 = __half22float2(*(__half2*)&vr.y);
        float2 v2 = __half22float2(*(__half2*)&vr.z);
        float2 v3 = __half22float2(*(__half2*)&vr.w);
        a0.x += ew * v0.x; a0.y += ew * v0.y; a0.z += ew * v1.x; a0.w += ew * v1.y;
        a1.x += ew * v2.x; a1.y += ew * v2.y; a1.z += ew * v3.x; a1.w += ew * v3.y;
    }
    float inv = (den > 0.f) ? (1.f / den) : 0.f;

    const float4* xp = (const float4*)(x + base);
    float4 x0 = xp[0], x1 = xp[1];
    float s_[8];
    s_[0] = x0.x + a0.x * inv; s_[1] = x0.y + a0.y * inv;
    s_[2] = x0.z + a0.z * inv; s_[3] = x0.w + a0.w * inv;
    s_[4] = x1.x + a1.x * inv; s_[5] = x1.y + a1.y * inv;
    s_[6] = x1.z + a1.z * inv; s_[7] = x1.w + a1.w * inv;
    float sum = 0.f, sq = 0.f;
#pragma unroll
    for (int j = 0; j < 8; j++) { sum += s_[j]; sq += s_[j] * s_[j]; }
#pragma unroll
    for (int o = 4; o; o >>= 1) {
        sum += __shfl_xor_sync(0xffffffffu, sum, o);
        sq  += __shfl_xor_sync(0xffffffffu, sq, o);
    }
    float mean = sum * (1.f / 64.f);
    float var = sq * (1.f / 64.f) - mean * mean;
    float rstd = rsqrtf(var + LN_EPS);
    float4 y0, y1;
    int c0 = h * 8;
    y0.x = (s_[0] - mean) * rstd * lg[c0 + 0] + lb[c0 + 0];
    y0.y = (s_[1] - mean) * rstd * lg[c0 + 1] + lb[c0 + 1];
    y0.z = (s_[2] - mean) * rstd * lg[c0 + 2] + lb[c0 + 2];
    y0.w = (s_[3] - mean) * rstd * lg[c0 + 3] + lb[c0 + 3];
    y1.x = (s_[4] - mean) * rstd * lg[c0 + 4] + lb[c0 + 4];
    y1.y = (s_[5] - mean) * rstd * lg[c0 + 5] + lb[c0 + 5];
    y1.z = (s_[6] - mean) * rstd * lg[c0 + 6] + lb[c0 + 6];
    y1.w = (s_[7] - mean) * rstd * lg[c0 + 7] + lb[c0 + 7];
    float4* op = (float4*)(g_x1 + base);
    op[0] = y0; op[1] = y1;
}

// ---------------- fused FFN: GEMM1(fp16) -> smem hid -> GEMM2(fp16) + residual + LN2 ----------------
__global__ __launch_bounds__(256, 2) void k_ffn(const float* __restrict__ w1,
                                                const float* __restrict__ b1,
                                                const float* __restrict__ w2,
                                                const float* __restrict__ b2,
                                                const float* __restrict__ lg,
                                                const float* __restrict__ lb,
                                                float* __restrict__ out) {
    __shared__ __align__(16) __half xh[16 * 72];       // fp16 x1 for GEMM1 A
    __shared__ __align__(16) float  xr[16 * 68];       // fp32 x1 for residual
    __shared__ __align__(16) __half hs[16 * 264];      // fp16 hidden
    __shared__ __align__(16) float  osum[2][16 * 68];
    int t = threadIdx.x;
    int wp = t >> 5, l = t & 31, gid = l >> 2, tig = l & 3;
    int kw = wp >> 2, nw2 = wp & 3;

    // GEMM1 B-frags: warp wp owns hid channels [wp*32, wp*32+32)
    unsigned b1fr[4][4][2];
#pragma unroll
    for (int nt = 0; nt < 4; nt++)
#pragma unroll
        for (int ks = 0; ks < 4; ks++)
            ldbh(b1fr[nt][ks], w1, ks * 16 + 2 * tig, wp * 32 + nt * 8 + gid, 256);
    float2 bias1[4];
#pragma unroll
    for (int nt = 0; nt < 4; nt++) {
        int ch0 = wp * 32 + nt * 8 + 2 * tig;
        bias1[nt] = make_float2(b1[ch0], b1[ch0 + 1]);
    }
    // GEMM2 B-frags: warp (kw, nw2): k half kw*128, out channels nw2*16..+16
    unsigned b2fr[2][8][2];
#pragma unroll
    for (int nt = 0; nt < 2; nt++)
#pragma unroll
        for (int ks = 0; ks < 8; ks++)
            ldbh(b2fr[nt][ks], w2, kw * 128 + ks * 16 + 2 * tig, nw2 * 16 + nt * 8 + gid, 64);
    int oh = t & 7;

    const int ngrp = N_NODES / 16;
    for (int p = blockIdx.x; p < ngrp; p += gridDim.x) {
        int n0 = p * 16;
        {   // stage x1: fp32 to xr, fp16 to xh
            float4 v = ((const float4*)(g_x1 + n0 * 64))[t];
            *(float4*)&xr[(t >> 4) * 68 + (t & 15) * 4] = v;
            __half2 hA = __floats2half2_rn(v.x, v.y), hB = __floats2half2_rn(v.z, v.w);
            *(uint2*)&xh[(t >> 4) * 72 + (t & 15) * 4] =
                make_uint2(*(unsigned*)&hA, *(unsigned*)&hB);
        }
        __syncthreads();
        // GEMM1: hid = relu(x1 @ w1 + b1) -> hs
        {
            float acc[4][4] = {{0.f,0.f,0.f,0.f},{0.f,0.f,0.f,0.f},
                               {0.f,0.f,0.f,0.f},{0.f,0.f,0.f,0.f}};
#pragma unroll
            for (int ks = 0; ks < 4; ks++) {
                unsigned a[4];
                ldah(a, &xh[gid * 72 + ks * 16 + 2 * tig], 72);
                mma16h(acc[0], a, b1fr[0][ks]);
                mma16h(acc[1], a, b1fr[1][ks]);
                mma16h(acc[2], a, b1fr[2][ks]);
                mma16h(acc[3], a, b1fr[3][ks]);
            }
#pragma unroll
            for (int nt = 0; nt < 4; nt++) {
                int ch0 = wp * 32 + nt * 8 + 2 * tig;
                *(__half2*)&hs[gid * 264 + ch0] =
                    __floats2half2_rn(fmaxf(acc[nt][0] + bias1[nt].x, 0.f),
                                      fmaxf(acc[nt][1] + bias1[nt].y, 0.f));
                *(__half2*)&hs[(gid + 8) * 264 + ch0] =
                    __floats2half2_rn(fmaxf(acc[nt][2] + bias1[nt].x, 0.f),
                                      fmaxf(acc[nt][3] + bias1[nt].y, 0.f));
            }
        }
        __syncthreads();
        // GEMM2: osum = hid @ w2 (k split across kw)
        {
            float acc[2][4] = {{0.f,0.f,0.f,0.f},{0.f,0.f,0.f,0.f}};
#pragma unroll
            for (int ks = 0; ks < 8; ks++) {
                unsigned a[4];
                ldah(a, &hs[gid * 264 + kw * 128 + ks * 16 + 2 * tig], 264);
                mma16h(acc[0], a, b2fr[0][ks]);
                mma16h(acc[1], a, b2fr[1][ks]);
            }
#pragma unroll
            for (int nt = 0; nt < 2; nt++) {
                int ch0 = nw2 * 16 + nt * 8 + 2 * tig;
                *(float2*)&osum[kw][gid * 68 + ch0]       = make_float2(acc[nt][0], acc[nt][1]);
                *(float2*)&osum[kw][(gid + 8) * 68 + ch0] = make_float2(acc[nt][2], acc[nt][3]);
            }
        }
        __syncthreads();
        // epilogue: residual + LN2 (threads 0..127: node=t>>3, oh=t&7)
        if (t < 128) {
            int node = t >> 3;
            int bi = node * 68 + oh * 8;
            float s[8];
#pragma unroll
            for (int j = 0; j < 8; j++)
                s[j] = xr[bi + j] + osum[0][bi + j] + osum[1][bi + j] + b2[oh * 8 + j];
            float sum = 0.f, sq = 0.f;
#pragma unroll
            for (int j = 0; j < 8; j++) { sum += s[j]; sq += s[j] * s[j]; }
#pragma unroll
            for (int o = 4; o; o >>= 1) {
                sum += __shfl_xor_sync(0xffffffffu, sum, o);
                sq  += __shfl_xor_sync(0xffffffffu, sq, o);
            }
            float mean = sum * (1.f / 64.f);
            float var = sq * (1.f / 64.f) - mean * mean;
            float rstd = rsqrtf(var + LN_EPS);
            float o8[8];
#pragma unroll
            for (int j = 0; j < 8; j++)
                o8[j] = (s[j] - mean) * rstd * lg[oh * 8 + j] + lb[oh * 8 + j];
            *(float4*)&out[(n0 + node) * 64 + oh * 8]     = *(float4*)&o8[0];
            *(float4*)&out[(n0 + node) * 64 + oh * 8 + 4] = *(float4*)&o8[4];
        }
        __syncthreads();
    }
}

extern "C" void kernel_launch(void* const* d_in, const int* in_sizes, int n_in,
                              void* d_out, int out_size) {
    const float* x      = (const float*)d_in[0];
    const void*  ei     = d_in[1];
    const float* attn_w = (const float*)d_in[2];
    const float* attn_b = (const float*)d_in[3];
    const float* w1     = (const float*)d_in[4];
    const float* b1     = (const float*)d_in[5];
    const float* w2     = (const float*)d_in[6];
    const float* b2     = (const float*)d_in[7];
    const float* ln1_g  = (const float*)d_in[8];
    const float* ln1_b  = (const float*)d_in[9];
    const float* ln2_g  = (const float*)d_in[10];
    const float* ln2_b  = (const float*)d_in[11];
    float* out = (float*)d_out;

    k_qkv<<<296, 256>>>(x, attn_w, attn_b, ei);
    k_scatter<<<N_EDGES / 256, 256>>>(ei);
    k_gather<<<N_NODES / 32, 256>>>(x, ln1_g, ln1_b);
    k_ffn<<<296, 256>>>(w1, b1, w2, b2, ln2_g, ln2_b, out);
}

// round 14
// speedup vs baseline: 4.6333x; 1.0479x over previous
#include <cuda_runtime.h>
#include <cuda_bf16.h>
#include <cuda_fp16.h>

#define N_NODES 100000
#define N_EDGES 1600000
#define EMBED 64
#define HEADS 8
#define FFN_DIM 256
#define LN_EPS 1e-5f
#define CAP 128

typedef unsigned long long u64;

// ---------------- fp16 mma.sync m16n8k16 ----------------
__device__ __forceinline__ void mma16h(float* acc, const unsigned* a, const unsigned* b) {
    asm volatile("mma.sync.aligned.m16n8k16.row.col.f32.f16.f16.f32 "
                 "{%0,%1,%2,%3},{%4,%5,%6,%7},{%8,%9},{%0,%1,%2,%3};"
                 : "+f"(acc[0]), "+f"(acc[1]), "+f"(acc[2]), "+f"(acc[3])
                 : "r"(a[0]), "r"(a[1]), "r"(a[2]), "r"(a[3]), "r"(b[0]), "r"(b[1]));
}
__device__ __forceinline__ void ldah(unsigned a[4], const __half* base, int S) {
    a[0] = *(const unsigned*)(base);
    a[1] = *(const unsigned*)(base + 8 * S);
    a[2] = *(const unsigned*)(base + 8);
    a[3] = *(const unsigned*)(base + 8 * S + 8);
}
__device__ __forceinline__ void ldbh(unsigned b[2], const float* W, int k0, int col, int ld) {
    __half2 h0 = __floats2half2_rn(W[(k0    ) * ld + col], W[(k0 + 1) * ld + col]);
    __half2 h1 = __floats2half2_rn(W[(k0 + 8) * ld + col], W[(k0 + 9) * ld + col]);
    b[0] = *(unsigned*)&h0;
    b[1] = *(unsigned*)&h1;
}

// ---------------- scratch ----------------
__device__ float  g_q[N_NODES * EMBED];
__device__ __half g_kh[N_NODES * EMBED];
__device__ __half g_vh[N_NODES * EMBED];
__device__ float  g_x1[N_NODES * EMBED];
__device__ int    g_cnt[N_NODES];
__device__ int    g_bcol[N_NODES * CAP];
__device__ int    g_is64;

// ---------------- QKV: fp16 mma; q fp32, k/v fp16 ----------------
__global__ __launch_bounds__(256, 2) void k_qkv(const float* __restrict__ x,
                                                const float* __restrict__ w,
                                                const float* __restrict__ b,
                                                const void* __restrict__ ei) {
    int t = threadIdx.x;
    for (int gi = blockIdx.x * 256 + t; gi < N_NODES; gi += gridDim.x * 256) g_cnt[gi] = 0;
    if (blockIdx.x == 0 && t == 0) {
        const unsigned* wr = (const unsigned*)ei;
        int is64 = 1;
        for (int q = 1; q < 256; q += 2) if (wr[q] != 0u) { is64 = 0; break; }
        g_is64 = is64;
    }
    __shared__ __align__(16) __half xh[2][32 * 72];
    int wp = t >> 5, l = t & 31, gid = l >> 2, tig = l & 3;
    int nb = wp * 24;
    unsigned bfr[3][4][2];
#pragma unroll
    for (int nt = 0; nt < 3; nt++)
#pragma unroll
        for (int ks = 0; ks < 4; ks++)
            ldbh(bfr[nt][ks], w, ks * 16 + 2 * tig, nb + nt * 8 + gid, 192);
    int seg[3], doff[3]; float2 bias[3];
#pragma unroll
    for (int nt = 0; nt < 3; nt++) {
        int ch0 = nb + nt * 8 + 2 * tig;
        int h = ch0 / 24, r = ch0 % 24;
        seg[nt] = (r < 8) ? 0 : ((r < 16) ? 1 : 2);
        doff[nt] = h * 8 + (r & 7);
        bias[nt] = make_float2(b[ch0], b[ch0 + 1]);
    }

    const int ngrp = N_NODES / 32;
    const int stride = gridDim.x;
    int p = blockIdx.x;
    if (p < ngrp) {
#pragma unroll
        for (int j = 0; j < 2; j++) {
            int i = t + j * 256;
            float4 v = ((const float4*)(x + p * 2048))[i];
            __half2 hA = __floats2half2_rn(v.x, v.y), hB = __floats2half2_rn(v.z, v.w);
            *(uint2*)&xh[0][(i >> 4) * 72 + (i & 15) * 4] =
                make_uint2(*(unsigned*)&hA, *(unsigned*)&hB);
        }
    }
    __syncthreads();
    for (int it = 0; p < ngrp; p += stride, it ^= 1) {
        int pn = p + stride;
        float4 nx0, nx1;
        if (pn < ngrp) {
            nx0 = ((const float4*)(x + pn * 2048))[t];
            nx1 = ((const float4*)(x + pn * 2048))[t + 256];
        }
        int n0 = p * 32;
#pragma unroll
        for (int mh = 0; mh < 2; mh++) {
            float acc[3][4] = {{0.f,0.f,0.f,0.f},{0.f,0.f,0.f,0.f},{0.f,0.f,0.f,0.f}};
#pragma unroll
            for (int ks = 0; ks < 4; ks++) {
                unsigned a[4];
                ldah(a, &xh[it][(mh * 16 + gid) * 72 + ks * 16 + 2 * tig], 72);
                mma16h(acc[0], a, bfr[0][ks]);
                mma16h(acc[1], a, bfr[1][ks]);
                mma16h(acc[2], a, bfr[2][ks]);
            }
            int na = n0 + mh * 16 + gid;
#pragma unroll
            for (int nt = 0; nt < 3; nt++) {
                float vx0 = acc[nt][0] + bias[nt].x, vy0 = acc[nt][1] + bias[nt].y;
                float vx1 = acc[nt][2] + bias[nt].x, vy1 = acc[nt][3] + bias[nt].y;
                if (seg[nt] == 0) {
                    *(float2*)&g_q[na * 64 + doff[nt]]       = make_float2(vx0, vy0);
                    *(float2*)&g_q[(na + 8) * 64 + doff[nt]] = make_float2(vx1, vy1);
                } else {
                    __half* base = (seg[nt] == 1) ? g_kh : g_vh;
                    *(__half2*)&base[na * 64 + doff[nt]]       = __floats2half2_rn(vx0, vy0);
                    *(__half2*)&base[(na + 8) * 64 + doff[nt]] = __floats2half2_rn(vx1, vy1);
                }
            }
        }
        if (pn < ngrp) {
            __half2 hA = __floats2half2_rn(nx0.x, nx0.y), hB = __floats2half2_rn(nx0.z, nx0.w);
            *(uint2*)&xh[it ^ 1][(t >> 4) * 72 + (t & 15) * 4] =
                make_uint2(*(unsigned*)&hA, *(unsigned*)&hB);
            int i = t + 256;
            hA = __floats2half2_rn(nx1.x, nx1.y); hB = __floats2half2_rn(nx1.z, nx1.w);
            *(uint2*)&xh[it ^ 1][(i >> 4) * 72 + (i & 15) * 4] =
                make_uint2(*(unsigned*)&hA, *(unsigned*)&hB);
        }
        __syncthreads();
    }
}

// ---------------- bucket scatter ----------------
__global__ void k_scatter(const void* __restrict__ ei_raw) {
    int e = blockIdx.x * blockDim.x + threadIdx.x;
    if (e >= N_EDGES) return;
    int r, c;
    if (g_is64) {
        const long long* ei = (const long long*)ei_raw;
        r = (int)ei[e]; c = (int)ei[N_EDGES + e];
    } else {
        const int* ei = (const int*)ei_raw;
        r = ei[e]; c = ei[N_EDGES + e];
    }
    int slot = atomicAdd(&g_cnt[r], 1);
    if (slot < CAP) g_bcol[r * CAP + slot] = c;
}

// ---------------- gather attention (fp16 k/v) + residual + LN1 ----------------
__global__ __launch_bounds__(256) void k_gather(const float* __restrict__ x,
                                                const float* __restrict__ lg,
                                                const float* __restrict__ lb) {
    int t = threadIdx.x;
    int n = blockIdx.x * 32 + (t >> 3);
    int h = t & 7;
    const int base = n * 64 + h * 8;
    const float4* qp = (const float4*)(g_q + base);
    float4 q0 = qp[0], q1 = qp[1];

    int deg = g_cnt[n];
    if (deg > CAP) deg = CAP;

    float den = 0.f;
    float4 a0 = make_float4(0.f, 0.f, 0.f, 0.f);
    float4 a1 = make_float4(0.f, 0.f, 0.f, 0.f);

    const int* bp = g_bcol + n * CAP;
    int cnext = (deg > 0) ? bp[0] : 0;
    for (int s = 0; s < deg; s++) {
        int c = cnext;
        cnext = (s + 1 < deg) ? bp[s + 1] : 0;
        uint4 kr = *(const uint4*)(g_kh + c * 64 + h * 8);
        uint4 vr = *(const uint4*)(g_vh + c * 64 + h * 8);
        float2 k0 = __half22float2(*(__half2*)&kr.x);
        float2 k1 = __half22float2(*(__half2*)&kr.y);
        float2 k2 = __half22float2(*(__half2*)&kr.z);
        float2 k3 = __half22float2(*(__half2*)&kr.w);
        float dot = q0.x * k0.x + q0.y * k0.y + q0.z * k1.x + q0.w * k1.y
                  + q1.x * k2.x + q1.y * k2.y + q1.z * k3.x + q1.w * k3.y;
        float ew = __expf(dot * 0.125f);
        den += ew;
        float2 v0 = __half22float2(*(__half2*)&vr.x);
        float2 v1 = __half22float2(*(__half2*)&vr.y);
        float2 v2 = __half22float2(*(__half2*)&vr.z);
        float2 v3 = __half22float2(*(__half2*)&vr.w);
        a0.x += ew * v0.x; a0.y += ew * v0.y; a0.z += ew * v1.x; a0.w += ew * v1.y;
        a1.x += ew * v2.x; a1.y += ew * v2.y; a1.z += ew * v3.x; a1.w += ew * v3.y;
    }
    float inv = (den > 0.f) ? (1.f / den) : 0.f;

    const float4* xp = (const float4*)(x + base);
    float4 x0 = xp[0], x1 = xp[1];
    float s_[8];
    s_[0] = x0.x + a0.x * inv; s_[1] = x0.y + a0.y * inv;
    s_[2] = x0.z + a0.z * inv; s_[3] = x0.w + a0.w * inv;
    s_[4] = x1.x + a1.x * inv; s_[5] = x1.y + a1.y * inv;
    s_[6] = x1.z + a1.z * inv; s_[7] = x1.w + a1.w * inv;
    float sum = 0.f, sq = 0.f;
#pragma unroll
    for (int j = 0; j < 8; j++) { sum += s_[j]; sq += s_[j] * s_[j]; }
#pragma unroll
    for (int o = 4; o; o >>= 1) {
        sum += __shfl_xor_sync(0xffffffffu, sum, o);
        sq  += __shfl_xor_sync(0xffffffffu, sq, o);
    }
    float mean = sum * (1.f / 64.f);
    float var = sq * (1.f / 64.f) - mean * mean;
    float rstd = rsqrtf(var + LN_EPS);
    float4 y0, y1;
    int c0 = h * 8;
    y0.x = (s_[0] - mean) * rstd * lg[c0 + 0] + lb[c0 + 0];
    y0.y = (s_[1] - mean) * rstd * lg[c0 + 1] + lb[c0 + 1];
    y0.z = (s_[2] - mean) * rstd * lg[c0 + 2] + lb[c0 + 2];
    y0.w = (s_[3] - mean) * rstd * lg[c0 + 3] + lb[c0 + 3];
    y1.x = (s_[4] - mean) * rstd * lg[c0 + 4] + lb[c0 + 4];
    y1.y = (s_[5] - mean) * rstd * lg[c0 + 5] + lb[c0 + 5];
    y1.z = (s_[6] - mean) * rstd * lg[c0 + 6] + lb[c0 + 6];
    y1.w = (s_[7] - mean) * rstd * lg[c0 + 7] + lb[c0 + 7];
    float4* op = (float4*)(g_x1 + base);
    op[0] = y0; op[1] = y1;
}

// ---------------- fused FFN: 32-node tiles, reg-prefetch, GEMM1+GEMM2+LN2 ----------------
__global__ __launch_bounds__(256, 2) void k_ffn(const float* __restrict__ w1,
                                                const float* __restrict__ b1,
                                                const float* __restrict__ w2,
                                                const float* __restrict__ b2,
                                                const float* __restrict__ lg,
                                                const float* __restrict__ lb,
                                                float* __restrict__ out) {
    __shared__ __align__(16) __half xh[32 * 72];       // 4.6 kB
    __shared__ __align__(16) float  xr[32 * 68];       // 8.7 kB
    __shared__ __align__(16) __half hs[32 * 264];      // 16.9 kB
    __shared__ __align__(16) float  osum[2][32 * 68];  // 17.4 kB
    int t = threadIdx.x;
    int wp = t >> 5, l = t & 31, gid = l >> 2, tig = l & 3;
    int kw = wp >> 2, nw2 = wp & 3;

    unsigned b1fr[4][4][2];
#pragma unroll
    for (int nt = 0; nt < 4; nt++)
#pragma unroll
        for (int ks = 0; ks < 4; ks++)
            ldbh(b1fr[nt][ks], w1, ks * 16 + 2 * tig, wp * 32 + nt * 8 + gid, 256);
    float2 bias1[4];
#pragma unroll
    for (int nt = 0; nt < 4; nt++) {
        int ch0 = wp * 32 + nt * 8 + 2 * tig;
        bias1[nt] = make_float2(b1[ch0], b1[ch0 + 1]);
    }
    unsigned b2fr[2][8][2];
#pragma unroll
    for (int nt = 0; nt < 2; nt++)
#pragma unroll
        for (int ks = 0; ks < 8; ks++)
            ldbh(b2fr[nt][ks], w2, kw * 128 + ks * 16 + 2 * tig, nw2 * 16 + nt * 8 + gid, 64);
    int oh = t & 7;

    const int ngrp = N_NODES / 32;   // 3125
    const int stride = gridDim.x;
    int p = blockIdx.x;
    if (p < ngrp) {
#pragma unroll
        for (int j = 0; j < 2; j++) {
            int i = t + j * 256;
            float4 v = ((const float4*)(g_x1 + p * 2048))[i];
            *(float4*)&xr[(i >> 4) * 68 + (i & 15) * 4] = v;
            __half2 hA = __floats2half2_rn(v.x, v.y), hB = __floats2half2_rn(v.z, v.w);
            *(uint2*)&xh[(i >> 4) * 72 + (i & 15) * 4] =
                make_uint2(*(unsigned*)&hA, *(unsigned*)&hB);
        }
    }
    __syncthreads();
    for (; p < ngrp; p += stride) {
        int pn = p + stride;
        float4 nx0, nx1;
        if (pn < ngrp) {
            nx0 = ((const float4*)(g_x1 + pn * 2048))[t];
            nx1 = ((const float4*)(g_x1 + pn * 2048))[t + 256];
        }
        int n0 = p * 32;
        // GEMM1: 32 nodes (two 16-row halves)
#pragma unroll
        for (int mh = 0; mh < 2; mh++) {
            float acc[4][4] = {{0.f,0.f,0.f,0.f},{0.f,0.f,0.f,0.f},
                               {0.f,0.f,0.f,0.f},{0.f,0.f,0.f,0.f}};
#pragma unroll
            for (int ks = 0; ks < 4; ks++) {
                unsigned a[4];
                ldah(a, &xh[(mh * 16 + gid) * 72 + ks * 16 + 2 * tig], 72);
                mma16h(acc[0], a, b1fr[0][ks]);
                mma16h(acc[1], a, b1fr[1][ks]);
                mma16h(acc[2], a, b1fr[2][ks]);
                mma16h(acc[3], a, b1fr[3][ks]);
            }
            int r0 = mh * 16 + gid;
#pragma unroll
            for (int nt = 0; nt < 4; nt++) {
                int ch0 = wp * 32 + nt * 8 + 2 * tig;
                *(__half2*)&hs[r0 * 264 + ch0] =
                    __floats2half2_rn(fmaxf(acc[nt][0] + bias1[nt].x, 0.f),
                                      fmaxf(acc[nt][1] + bias1[nt].y, 0.f));
                *(__half2*)&hs[(r0 + 8) * 264 + ch0] =
                    __floats2half2_rn(fmaxf(acc[nt][2] + bias1[nt].x, 0.f),
                                      fmaxf(acc[nt][3] + bias1[nt].y, 0.f));
            }
        }
        __syncthreads();
        // GEMM2: k-split across kw, 32 nodes
#pragma unroll
        for (int mh = 0; mh < 2; mh++) {
            float acc[2][4] = {{0.f,0.f,0.f,0.f},{0.f,0.f,0.f,0.f}};
#pragma unroll
            for (int ks = 0; ks < 8; ks++) {
                unsigned a[4];
                ldah(a, &hs[(mh * 16 + gid) * 264 + kw * 128 + ks * 16 + 2 * tig], 264);
                mma16h(acc[0], a, b2fr[0][ks]);
                mma16h(acc[1], a, b2fr[1][ks]);
            }
            int r0 = mh * 16 + gid;
#pragma unroll
            for (int nt = 0; nt < 2; nt++) {
                int ch0 = nw2 * 16 + nt * 8 + 2 * tig;
                *(float2*)&osum[kw][r0 * 68 + ch0]       = make_float2(acc[nt][0], acc[nt][1]);
                *(float2*)&osum[kw][(r0 + 8) * 68 + ch0] = make_float2(acc[nt][2], acc[nt][3]);
            }
        }
        __syncthreads();
        // epilogue: 256 threads, node = t>>3 (0..31), oh = t&7
        {
            int node = t >> 3;
            int bi = node * 68 + oh * 8;
            float s[8];
#pragma unroll
            for (int j = 0; j < 8; j++)
                s[j] = xr[bi + j] + osum[0][bi + j] + osum[1][bi + j] + b2[oh * 8 + j];
            float sum = 0.f, sq = 0.f;
#pragma unroll
            for (int j = 0; j < 8; j++) { sum += s[j]; sq += s[j] * s[j]; }
#pragma unroll
            for (int o = 4; o; o >>= 1) {
                sum += __shfl_xor_sync(0xffffffffu, sum, o);
                sq  += __shfl_xor_sync(0xffffffffu, sq, o);
            }
            float mean = sum * (1.f / 64.f);
            float var = sq * (1.f / 64.f) - mean * mean;
            float rstd = rsqrtf(var + LN_EPS);
            float o8[8];
#pragma unroll
            for (int j = 0; j < 8; j++)
                o8[j] = (s[j] - mean) * rstd * lg[oh * 8 + j] + lb[oh * 8 + j];
            *(float4*)&out[(n0 + node) * 64 + oh * 8]     = *(float4*)&o8[0];
            *(float4*)&out[(n0 + node) * 64 + oh * 8 + 4] = *(float4*)&o8[4];
        }
        __syncthreads();
        // stage next tile (regs -> smem)
        if (pn < ngrp) {
#pragma unroll
            for (int j = 0; j < 2; j++) {
                int i = t + j * 256;
                float4 v = (j == 0) ? nx0 : nx1;
                *(float4*)&xr[(i >> 4) * 68 + (i & 15) * 4] = v;
                __half2 hA = __floats2half2_rn(v.x, v.y), hB = __floats2half2_rn(v.z, v.w);
                *(uint2*)&xh[(i >> 4) * 72 + (i & 15) * 4] =
                    make_uint2(*(unsigned*)&hA, *(unsigned*)&hB);
            }
        }
        __syncthreads();
    }
}

extern "C" void kernel_launch(void* const* d_in, const int* in_sizes, int n_in,
                              void* d_out, int out_size) {
    const float* x      = (const float*)d_in[0];
    const void*  ei     = d_in[1];
    const float* attn_w = (const float*)d_in[2];
    const float* attn_b = (const float*)d_in[3];
    const float* w1     = (const float*)d_in[4];
    const float* b1     = (const float*)d_in[5];
    const float* w2     = (const float*)d_in[6];
    const float* b2     = (const float*)d_in[7];
    const float* ln1_g  = (const float*)d_in[8];
    const float* ln1_b  = (const float*)d_in[9];
    const float* ln2_g  = (const float*)d_in[10];
    const float* ln2_b  = (const float*)d_in[11];
    float* out = (float*)d_out;

    k_qkv<<<296, 256>>>(x, attn_w, attn_b, ei);
    k_scatter<<<N_EDGES / 256, 256>>>(ei);
    k_gather<<<N_NODES / 32, 256>>>(x, ln1_g, ln1_b);
    k_ffn<<<296, 256>>>(w1, b1, w2, b2, ln2_g, ln2_b, out);
}

// round 15
// speedup vs baseline: 4.6623x; 1.0063x over previous
#include <cuda_runtime.h>
#include <cuda_bf16.h>
#include <cuda_fp16.h>

#define N_NODES 100000
#define N_EDGES 1600000
#define EMBED 64
#define HEADS 8
#define FFN_DIM 256
#define LN_EPS 1e-5f
#define CAP 128

typedef unsigned long long u64;

// ---------------- fp16 mma.sync m16n8k16 ----------------
__device__ __forceinline__ void mma16h(float* acc, const unsigned* a, const unsigned* b) {
    asm volatile("mma.sync.aligned.m16n8k16.row.col.f32.f16.f16.f32 "
                 "{%0,%1,%2,%3},{%4,%5,%6,%7},{%8,%9},{%0,%1,%2,%3};"
                 : "+f"(acc[0]), "+f"(acc[1]), "+f"(acc[2]), "+f"(acc[3])
                 : "r"(a[0]), "r"(a[1]), "r"(a[2]), "r"(a[3]), "r"(b[0]), "r"(b[1]));
}
// ldmatrix x4: full m16k16 A fragment in ONE LSU op (lane ptr precomputed)
__device__ __forceinline__ void ldmat4(unsigned a[4], const __half* p) {
    unsigned addr = (unsigned)__cvta_generic_to_shared(p);
    asm volatile("ldmatrix.sync.aligned.m8n8.x4.shared.b16 {%0,%1,%2,%3}, [%4];"
                 : "=r"(a[0]), "=r"(a[1]), "=r"(a[2]), "=r"(a[3]) : "r"(addr));
}
__device__ __forceinline__ void ldbh(unsigned b[2], const float* W, int k0, int col, int ld) {
    __half2 h0 = __floats2half2_rn(W[(k0    ) * ld + col], W[(k0 + 1) * ld + col]);
    __half2 h1 = __floats2half2_rn(W[(k0 + 8) * ld + col], W[(k0 + 9) * ld + col]);
    b[0] = *(unsigned*)&h0;
    b[1] = *(unsigned*)&h1;
}

// ---------------- scratch ----------------
__device__ float  g_q[N_NODES * EMBED];
__device__ __half g_kh[N_NODES * EMBED];
__device__ __half g_vh[N_NODES * EMBED];
__device__ float  g_x1[N_NODES * EMBED];
__device__ int    g_cnt[N_NODES];
__device__ int    g_bcol[N_NODES * CAP];
__device__ int    g_is64;

// ---------------- QKV: fp16 mma + ldmatrix; q fp32, k/v fp16 ----------------
__global__ __launch_bounds__(256, 2) void k_qkv(const float* __restrict__ x,
                                                const float* __restrict__ w,
                                                const float* __restrict__ b,
                                                const void* __restrict__ ei) {
    int t = threadIdx.x;
    for (int gi = blockIdx.x * 256 + t; gi < N_NODES; gi += gridDim.x * 256) g_cnt[gi] = 0;
    if (blockIdx.x == 0 && t == 0) {
        const unsigned* wr = (const unsigned*)ei;
        int is64 = 1;
        for (int q = 1; q < 256; q += 2) if (wr[q] != 0u) { is64 = 0; break; }
        g_is64 = is64;
    }
    __shared__ __align__(16) __half xh[2][32 * 72];
    int wp = t >> 5, l = t & 31, gid = l >> 2, tig = l & 3;
    int nb = wp * 24;
    // ldmatrix per-lane offset within a 16x16 tile (stride 72)
    int lmoff72 = (((l >> 3) & 1) * 8 + (l & 7)) * 72 + (l >> 4) * 8;
    unsigned bfr[3][4][2];
#pragma unroll
    for (int nt = 0; nt < 3; nt++)
#pragma unroll
        for (int ks = 0; ks < 4; ks++)
            ldbh(bfr[nt][ks], w, ks * 16 + 2 * tig, nb + nt * 8 + gid, 192);
    int seg[3], doff[3]; float2 bias[3];
#pragma unroll
    for (int nt = 0; nt < 3; nt++) {
        int ch0 = nb + nt * 8 + 2 * tig;
        int h = ch0 / 24, r = ch0 % 24;
        seg[nt] = (r < 8) ? 0 : ((r < 16) ? 1 : 2);
        doff[nt] = h * 8 + (r & 7);
        bias[nt] = make_float2(b[ch0], b[ch0 + 1]);
    }

    const int ngrp = N_NODES / 32;
    const int stride = gridDim.x;
    int p = blockIdx.x;
    if (p < ngrp) {
#pragma unroll
        for (int j = 0; j < 2; j++) {
            int i = t + j * 256;
            float4 v = ((const float4*)(x + p * 2048))[i];
            __half2 hA = __floats2half2_rn(v.x, v.y), hB = __floats2half2_rn(v.z, v.w);
            *(uint2*)&xh[0][(i >> 4) * 72 + (i & 15) * 4] =
                make_uint2(*(unsigned*)&hA, *(unsigned*)&hB);
        }
    }
    __syncthreads();
    for (int it = 0; p < ngrp; p += stride, it ^= 1) {
        int pn = p + stride;
        float4 nx0, nx1;
        if (pn < ngrp) {
            nx0 = ((const float4*)(x + pn * 2048))[t];
            nx1 = ((const float4*)(x + pn * 2048))[t + 256];
        }
        int n0 = p * 32;
#pragma unroll
        for (int mh = 0; mh < 2; mh++) {
            float acc[3][4] = {{0.f,0.f,0.f,0.f},{0.f,0.f,0.f,0.f},{0.f,0.f,0.f,0.f}};
            const __half* tb = &xh[it][(mh * 16) * 72] + lmoff72;
#pragma unroll
            for (int ks = 0; ks < 4; ks++) {
                unsigned a[4];
                ldmat4(a, tb + ks * 16);
                mma16h(acc[0], a, bfr[0][ks]);
                mma16h(acc[1], a, bfr[1][ks]);
                mma16h(acc[2], a, bfr[2][ks]);
            }
            int na = n0 + mh * 16 + gid;
#pragma unroll
            for (int nt = 0; nt < 3; nt++) {
                float vx0 = acc[nt][0] + bias[nt].x, vy0 = acc[nt][1] + bias[nt].y;
                float vx1 = acc[nt][2] + bias[nt].x, vy1 = acc[nt][3] + bias[nt].y;
                if (seg[nt] == 0) {
                    *(float2*)&g_q[na * 64 + doff[nt]]       = make_float2(vx0, vy0);
                    *(float2*)&g_q[(na + 8) * 64 + doff[nt]] = make_float2(vx1, vy1);
                } else {
                    __half* base = (seg[nt] == 1) ? g_kh : g_vh;
                    *(__half2*)&base[na * 64 + doff[nt]]       = __floats2half2_rn(vx0, vy0);
                    *(__half2*)&base[(na + 8) * 64 + doff[nt]] = __floats2half2_rn(vx1, vy1);
                }
            }
        }
        if (pn < ngrp) {
            __half2 hA = __floats2half2_rn(nx0.x, nx0.y), hB = __floats2half2_rn(nx0.z, nx0.w);
            *(uint2*)&xh[it ^ 1][(t >> 4) * 72 + (t & 15) * 4] =
                make_uint2(*(unsigned*)&hA, *(unsigned*)&hB);
            int i = t + 256;
            hA = __floats2half2_rn(nx1.x, nx1.y); hB = __floats2half2_rn(nx1.z, nx1.w);
            *(uint2*)&xh[it ^ 1][(i >> 4) * 72 + (i & 15) * 4] =
                make_uint2(*(unsigned*)&hA, *(unsigned*)&hB);
        }
        __syncthreads();
    }
}

// ---------------- bucket scatter ----------------
__global__ void k_scatter(const void* __restrict__ ei_raw) {
    int e = blockIdx.x * blockDim.x + threadIdx.x;
    if (e >= N_EDGES) return;
    int r, c;
    if (g_is64) {
        const long long* ei = (const long long*)ei_raw;
        r = (int)ei[e]; c = (int)ei[N_EDGES + e];
    } else {
        const int* ei = (const int*)ei_raw;
        r = ei[e]; c = ei[N_EDGES + e];
    }
    int slot = atomicAdd(&g_cnt[r], 1);
    if (slot < CAP) g_bcol[r * CAP + slot] = c;
}

// ---------------- gather attention (fp16 k/v) + residual + LN1 ----------------
__global__ __launch_bounds__(256) void k_gather(const float* __restrict__ x,
                                                const float* __restrict__ lg,
                                                const float* __restrict__ lb) {
    int t = threadIdx.x;
    int n = blockIdx.x * 32 + (t >> 3);
    int h = t & 7;
    const int base = n * 64 + h * 8;
    const float4* qp = (const float4*)(g_q + base);
    float4 q0 = qp[0], q1 = qp[1];

    int deg = g_cnt[n];
    if (deg > CAP) deg = CAP;

    float den = 0.f;
    float4 a0 = make_float4(0.f, 0.f, 0.f, 0.f);
    float4 a1 = make_float4(0.f, 0.f, 0.f, 0.f);

    const int* bp = g_bcol + n * CAP;
    int cnext = (deg > 0) ? bp[0] : 0;
    for (int s = 0; s < deg; s++) {
        int c = cnext;
        cnext = (s + 1 < deg) ? bp[s + 1] : 0;
        uint4 kr = *(const uint4*)(g_kh + c * 64 + h * 8);
        uint4 vr = *(const uint4*)(g_vh + c * 64 + h * 8);
        float2 k0 = __half22float2(*(__half2*)&kr.x);
        float2 k1 = __half22float2(*(__half2*)&kr.y);
        float2 k2 = __half22float2(*(__half2*)&kr.z);
        float2 k3 = __half22float2(*(__half2*)&kr.w);
        float dot = q0.x * k0.x + q0.y * k0.y + q0.z * k1.x + q0.w * k1.y
                  + q1.x * k2.x + q1.y * k2.y + q1.z * k3.x + q1.w * k3.y;
        float ew = __expf(dot * 0.125f);
        den += ew;
        float2 v0 = __half22float2(*(__half2*)&vr.x);
        float2 v1 = __half22float2(*(__half2*)&vr.y);
        float2 v2 = __half22float2(*(__half2*)&vr.z);
        float2 v3 = __half22float2(*(__half2*)&vr.w);
        a0.x += ew * v0.x; a0.y += ew * v0.y; a0.z += ew * v1.x; a0.w += ew * v1.y;
        a1.x += ew * v2.x; a1.y += ew * v2.y; a1.z += ew * v3.x; a1.w += ew * v3.y;
    }
    float inv = (den > 0.f) ? (1.f / den) : 0.f;

    const float4* xp = (const float4*)(x + base);
    float4 x0 = xp[0], x1 = xp[1];
    float s_[8];
    s_[0] = x0.x + a0.x * inv; s_[1] = x0.y + a0.y * inv;
    s_[2] = x0.z + a0.z * inv; s_[3] = x0.w + a0.w * inv;
    s_[4] = x1.x + a1.x * inv; s_[5] = x1.y + a1.y * inv;
    s_[6] = x1.z + a1.z * inv; s_[7] = x1.w + a1.w * inv;
    float sum = 0.f, sq = 0.f;
#pragma unroll
    for (int j = 0; j < 8; j++) { sum += s_[j]; sq += s_[j] * s_[j]; }
#pragma unroll
    for (int o = 4; o; o >>= 1) {
        sum += __shfl_xor_sync(0xffffffffu, sum, o);
        sq  += __shfl_xor_sync(0xffffffffu, sq, o);
    }
    float mean = sum * (1.f / 64.f);
    float var = sq * (1.f / 64.f) - mean * mean;
    float rstd = rsqrtf(var + LN_EPS);
    float4 y0, y1;
    int c0 = h * 8;
    y0.x = (s_[0] - mean) * rstd * lg[c0 + 0] + lb[c0 + 0];
    y0.y = (s_[1] - mean) * rstd * lg[c0 + 1] + lb[c0 + 1];
    y0.z = (s_[2] - mean) * rstd * lg[c0 + 2] + lb[c0 + 2];
    y0.w = (s_[3] - mean) * rstd * lg[c0 + 3] + lb[c0 + 3];
    y1.x = (s_[4] - mean) * rstd * lg[c0 + 4] + lb[c0 + 4];
    y1.y = (s_[5] - mean) * rstd * lg[c0 + 5] + lb[c0 + 5];
    y1.z = (s_[6] - mean) * rstd * lg[c0 + 6] + lb[c0 + 6];
    y1.w = (s_[7] - mean) * rstd * lg[c0 + 7] + lb[c0 + 7];
    float4* op = (float4*)(g_x1 + base);
    op[0] = y0; op[1] = y1;
}

// ---------------- fused FFN: 32-node tiles + ldmatrix, GEMM1+GEMM2+LN2 ----------------
__global__ __launch_bounds__(256, 2) void k_ffn(const float* __restrict__ w1,
                                                const float* __restrict__ b1,
                                                const float* __restrict__ w2,
                                                const float* __restrict__ b2,
                                                const float* __restrict__ lg,
                                                const float* __restrict__ lb,
                                                float* __restrict__ out) {
    __shared__ __align__(16) __half xh[32 * 72];
    __shared__ __align__(16) float  xr[32 * 68];
    __shared__ __align__(16) __half hs[32 * 264];
    __shared__ __align__(16) float  osum[2][32 * 68];
    int t = threadIdx.x;
    int wp = t >> 5, l = t & 31, gid = l >> 2, tig = l & 3;
    int kw = wp >> 2, nw2 = wp & 3;
    int lmrow = ((l >> 3) & 1) * 8 + (l & 7);
    int lmk = (l >> 4) * 8;
    int lmoff72  = lmrow * 72  + lmk;
    int lmoff264 = lmrow * 264 + lmk;

    unsigned b1fr[4][4][2];
#pragma unroll
    for (int nt = 0; nt < 4; nt++)
#pragma unroll
        for (int ks = 0; ks < 4; ks++)
            ldbh(b1fr[nt][ks], w1, ks * 16 + 2 * tig, wp * 32 + nt * 8 + gid, 256);
    float2 bias1[4];
#pragma unroll
    for (int nt = 0; nt < 4; nt++) {
        int ch0 = wp * 32 + nt * 8 + 2 * tig;
        bias1[nt] = make_float2(b1[ch0], b1[ch0 + 1]);
    }
    unsigned b2fr[2][8][2];
#pragma unroll
    for (int nt = 0; nt < 2; nt++)
#pragma unroll
        for (int ks = 0; ks < 8; ks++)
            ldbh(b2fr[nt][ks], w2, kw * 128 + ks * 16 + 2 * tig, nw2 * 16 + nt * 8 + gid, 64);
    int oh = t & 7;

    const int ngrp = N_NODES / 32;
    const int stride = gridDim.x;
    int p = blockIdx.x;
    if (p < ngrp) {
#pragma unroll
        for (int j = 0; j < 2; j++) {
            int i = t + j * 256;
            float4 v = ((const float4*)(g_x1 + p * 2048))[i];
            *(float4*)&xr[(i >> 4) * 68 + (i & 15) * 4] = v;
            __half2 hA = __floats2half2_rn(v.x, v.y), hB = __floats2half2_rn(v.z, v.w);
            *(uint2*)&xh[(i >> 4) * 72 + (i & 15) * 4] =
                make_uint2(*(unsigned*)&hA, *(unsigned*)&hB);
        }
    }
    __syncthreads();
    for (; p < ngrp; p += stride) {
        int pn = p + stride;
        float4 nx0, nx1;
        if (pn < ngrp) {
            nx0 = ((const float4*)(g_x1 + pn * 2048))[t];
            nx1 = ((const float4*)(g_x1 + pn * 2048))[t + 256];
        }
        int n0 = p * 32;
        // GEMM1
#pragma unroll
        for (int mh = 0; mh < 2; mh++) {
            float acc[4][4] = {{0.f,0.f,0.f,0.f},{0.f,0.f,0.f,0.f},
                               {0.f,0.f,0.f,0.f},{0.f,0.f,0.f,0.f}};
            const __half* tb = &xh[(mh * 16) * 72] + lmoff72;
#pragma unroll
            for (int ks = 0; ks < 4; ks++) {
                unsigned a[4];
                ldmat4(a, tb + ks * 16);
                mma16h(acc[0], a, b1fr[0][ks]);
                mma16h(acc[1], a, b1fr[1][ks]);
                mma16h(acc[2], a, b1fr[2][ks]);
                mma16h(acc[3], a, b1fr[3][ks]);
            }
            int r0 = mh * 16 + gid;
#pragma unroll
            for (int nt = 0; nt < 4; nt++) {
                int ch0 = wp * 32 + nt * 8 + 2 * tig;
                *(__half2*)&hs[r0 * 264 + ch0] =
                    __floats2half2_rn(fmaxf(acc[nt][0] + bias1[nt].x, 0.f),
                                      fmaxf(acc[nt][1] + bias1[nt].y, 0.f));
                *(__half2*)&hs[(r0 + 8) * 264 + ch0] =
                    __floats2half2_rn(fmaxf(acc[nt][2] + bias1[nt].x, 0.f),
                                      fmaxf(acc[nt][3] + bias1[nt].y, 0.f));
            }
        }
        __syncthreads();
        // GEMM2
#pragma unroll
        for (int mh = 0; mh < 2; mh++) {
            float acc[2][4] = {{0.f,0.f,0.f,0.f},{0.f,0.f,0.f,0.f}};
            const __half* tb = &hs[(mh * 16) * 264 + kw * 128] + lmoff264;
#pragma unroll
            for (int ks = 0; ks < 8; ks++) {
                unsigned a[4];
                ldmat4(a, tb + ks * 16);
                mma16h(acc[0], a, b2fr[0][ks]);
                mma16h(acc[1], a, b2fr[1][ks]);
            }
            int r0 = mh * 16 + gid;
#pragma unroll
            for (int nt = 0; nt < 2; nt++) {
                int ch0 = nw2 * 16 + nt * 8 + 2 * tig;
                *(float2*)&osum[kw][r0 * 68 + ch0]       = make_float2(acc[nt][0], acc[nt][1]);
                *(float2*)&osum[kw][(r0 + 8) * 68 + ch0] = make_float2(acc[nt][2], acc[nt][3]);
            }
        }
        __syncthreads();
        // epilogue
        {
            int node = t >> 3;
            int bi = node * 68 + oh * 8;
            float s[8];
#pragma unroll
            for (int j = 0; j < 8; j++)
                s[j] = xr[bi + j] + osum[0][bi + j] + osum[1][bi + j] + b2[oh * 8 + j];
            float sum = 0.f, sq = 0.f;
#pragma unroll
            for (int j = 0; j < 8; j++) { sum += s[j]; sq += s[j] * s[j]; }
#pragma unroll
            for (int o = 4; o; o >>= 1) {
                sum += __shfl_xor_sync(0xffffffffu, sum, o);
                sq  += __shfl_xor_sync(0xffffffffu, sq, o);
            }
            float mean = sum * (1.f / 64.f);
            float var = sq * (1.f / 64.f) - mean * mean;
            float rstd = rsqrtf(var + LN_EPS);
            float o8[8];
#pragma unroll
            for (int j = 0; j < 8; j++)
                o8[j] = (s[j] - mean) * rstd * lg[oh * 8 + j] + lb[oh * 8 + j];
            *(float4*)&out[(n0 + node) * 64 + oh * 8]     = *(float4*)&o8[0];
            *(float4*)&out[(n0 + node) * 64 + oh * 8 + 4] = *(float4*)&o8[4];
        }
        __syncthreads();
        if (pn < ngrp) {
#pragma unroll
            for (int j = 0; j < 2; j++) {
                int i = t + j * 256;
                float4 v = (j == 0) ? nx0 : nx1;
                *(float4*)&xr[(i >> 4) * 68 + (i & 15) * 4] = v;
                __half2 hA = __floats2half2_rn(v.x, v.y), hB = __floats2half2_rn(v.z, v.w);
                *(uint2*)&xh[(i >> 4) * 72 + (i & 15) * 4] =
                    make_uint2(*(unsigned*)&hA, *(unsigned*)&hB);
            }
        }
        __syncthreads();
    }
}

extern "C" void kernel_launch(void* const* d_in, const int* in_sizes, int n_in,
                              void* d_out, int out_size) {
    const float* x      = (const float*)d_in[0];
    const void*  ei     = d_in[1];
    const float* attn_w = (const float*)d_in[2];
    const float* attn_b = (const float*)d_in[3];
    const float* w1     = (const float*)d_in[4];
    const float* b1     = (const float*)d_in[5];
    const float* w2     = (const float*)d_in[6];
    const float* b2     = (const float*)d_in[7];
    const float* ln1_g  = (const float*)d_in[8];
    const float* ln1_b  = (const float*)d_in[9];
    const float* ln2_g  = (const float*)d_in[10];
    const float* ln2_b  = (const float*)d_in[11];
    float* out = (float*)d_out;

    k_qkv<<<296, 256>>>(x, attn_w, attn_b, ei);
    k_scatter<<<N_EDGES / 256, 256>>>(ei);
    k_gather<<<N_NODES / 32, 256>>>(x, ln1_g, ln1_b);
    k_ffn<<<296, 256>>>(w1, b1, w2, b2, ln2_g, ln2_b, out);
}

// round 16
// speedup vs baseline: 4.6951x; 1.0070x over previous
#include <cuda_runtime.h>
#include <cuda_bf16.h>
#include <cuda_fp16.h>

#define N_NODES 100000
#define N_EDGES 1600000
#define EMBED 64
#define HEADS 8
#define FFN_DIM 256
#define LN_EPS 1e-5f
#define CAP 128

typedef unsigned long long u64;

// ---------------- fp16 mma.sync m16n8k16 ----------------
__device__ __forceinline__ void mma16h(float* acc, const unsigned* a, const unsigned* b) {
    asm volatile("mma.sync.aligned.m16n8k16.row.col.f32.f16.f16.f32 "
                 "{%0,%1,%2,%3},{%4,%5,%6,%7},{%8,%9},{%0,%1,%2,%3};"
                 : "+f"(acc[0]), "+f"(acc[1]), "+f"(acc[2]), "+f"(acc[3])
                 : "r"(a[0]), "r"(a[1]), "r"(a[2]), "r"(a[3]), "r"(b[0]), "r"(b[1]));
}
__device__ __forceinline__ void ldmat4(unsigned a[4], const __half* p) {
    unsigned addr = (unsigned)__cvta_generic_to_shared(p);
    asm volatile("ldmatrix.sync.aligned.m8n8.x4.shared.b16 {%0,%1,%2,%3}, [%4];"
                 : "=r"(a[0]), "=r"(a[1]), "=r"(a[2]), "=r"(a[3]) : "r"(addr));
}
__device__ __forceinline__ void ldbh(unsigned b[2], const float* W, int k0, int col, int ld) {
    __half2 h0 = __floats2half2_rn(W[(k0    ) * ld + col], W[(k0 + 1) * ld + col]);
    __half2 h1 = __floats2half2_rn(W[(k0 + 8) * ld + col], W[(k0 + 9) * ld + col]);
    b[0] = *(unsigned*)&h0;
    b[1] = *(unsigned*)&h1;
}

// ---------------- scratch ----------------
__device__ float  g_q[N_NODES * EMBED];
__device__ __half g_kh[N_NODES * EMBED];
__device__ __half g_vh[N_NODES * EMBED];
__device__ float  g_x1[N_NODES * EMBED];
__device__ int    g_cnt[N_NODES];
__device__ int    g_bcol[N_NODES * CAP];
__device__ int    g_is64;

// ---------------- init: zero counters + index dtype probe ----------------
__global__ void k_init(const void* __restrict__ ei) {
    int i = blockIdx.x * blockDim.x + threadIdx.x;
    if (i < N_NODES) g_cnt[i] = 0;
    if (i == 0) {
        const unsigned* wr = (const unsigned*)ei;
        int is64 = 1;
        for (int q = 1; q < 256; q += 2) if (wr[q] != 0u) { is64 = 0; break; }
        g_is64 = is64;
    }
}

// ---------------- QKV: fp16 mma + ldmatrix; q fp32, k/v fp16 ----------------
__global__ __launch_bounds__(256, 2) void k_qkv(const float* __restrict__ x,
                                                const float* __restrict__ w,
                                                const float* __restrict__ b) {
    int t = threadIdx.x;
    __shared__ __align__(16) __half xh[2][32 * 72];
    int wp = t >> 5, l = t & 31, gid = l >> 2, tig = l & 3;
    int nb = wp * 24;
    int lmoff72 = (((l >> 3) & 1) * 8 + (l & 7)) * 72 + (l >> 4) * 8;
    unsigned bfr[3][4][2];
#pragma unroll
    for (int nt = 0; nt < 3; nt++)
#pragma unroll
        for (int ks = 0; ks < 4; ks++)
            ldbh(bfr[nt][ks], w, ks * 16 + 2 * tig, nb + nt * 8 + gid, 192);
    int seg[3], doff[3]; float2 bias[3];
#pragma unroll
    for (int nt = 0; nt < 3; nt++) {
        int ch0 = nb + nt * 8 + 2 * tig;
        int h = ch0 / 24, r = ch0 % 24;
        seg[nt] = (r < 8) ? 0 : ((r < 16) ? 1 : 2);
        doff[nt] = h * 8 + (r & 7);
        bias[nt] = make_float2(b[ch0], b[ch0 + 1]);
    }

    const int ngrp = N_NODES / 32;
    const int stride = gridDim.x;
    int p = blockIdx.x;
    if (p < ngrp) {
#pragma unroll
        for (int j = 0; j < 2; j++) {
            int i = t + j * 256;
            float4 v = ((const float4*)(x + p * 2048))[i];
            __half2 hA = __floats2half2_rn(v.x, v.y), hB = __floats2half2_rn(v.z, v.w);
            *(uint2*)&xh[0][(i >> 4) * 72 + (i & 15) * 4] =
                make_uint2(*(unsigned*)&hA, *(unsigned*)&hB);
        }
    }
    __syncthreads();
    for (int it = 0; p < ngrp; p += stride, it ^= 1) {
        int pn = p + stride;
        float4 nx0, nx1;
        if (pn < ngrp) {
            nx0 = ((const float4*)(x + pn * 2048))[t];
            nx1 = ((const float4*)(x + pn * 2048))[t + 256];
        }
        int n0 = p * 32;
#pragma unroll
        for (int mh = 0; mh < 2; mh++) {
            float acc[3][4] = {{0.f,0.f,0.f,0.f},{0.f,0.f,0.f,0.f},{0.f,0.f,0.f,0.f}};
            const __half* tb = &xh[it][(mh * 16) * 72] + lmoff72;
#pragma unroll
            for (int ks = 0; ks < 4; ks++) {
                unsigned a[4];
                ldmat4(a, tb + ks * 16);
                mma16h(acc[0], a, bfr[0][ks]);
                mma16h(acc[1], a, bfr[1][ks]);
                mma16h(acc[2], a, bfr[2][ks]);
            }
            int na = n0 + mh * 16 + gid;
#pragma unroll
            for (int nt = 0; nt < 3; nt++) {
                float vx0 = acc[nt][0] + bias[nt].x, vy0 = acc[nt][1] + bias[nt].y;
                float vx1 = acc[nt][2] + bias[nt].x, vy1 = acc[nt][3] + bias[nt].y;
                if (seg[nt] == 0) {
                    *(float2*)&g_q[na * 64 + doff[nt]]       = make_float2(vx0, vy0);
                    *(float2*)&g_q[(na + 8) * 64 + doff[nt]] = make_float2(vx1, vy1);
                } else {
                    __half* base = (seg[nt] == 1) ? g_kh : g_vh;
                    *(__half2*)&base[na * 64 + doff[nt]]       = __floats2half2_rn(vx0, vy0);
                    *(__half2*)&base[(na + 8) * 64 + doff[nt]] = __floats2half2_rn(vx1, vy1);
                }
            }
        }
        if (pn < ngrp) {
            __half2 hA = __floats2half2_rn(nx0.x, nx0.y), hB = __floats2half2_rn(nx0.z, nx0.w);
            *(uint2*)&xh[it ^ 1][(t >> 4) * 72 + (t & 15) * 4] =
                make_uint2(*(unsigned*)&hA, *(unsigned*)&hB);
            int i = t + 256;
            hA = __floats2half2_rn(nx1.x, nx1.y); hB = __floats2half2_rn(nx1.z, nx1.w);
            *(uint2*)&xh[it ^ 1][(i >> 4) * 72 + (i & 15) * 4] =
                make_uint2(*(unsigned*)&hA, *(unsigned*)&hB);
        }
        __syncthreads();
    }
}

// ---------------- bucket scatter ----------------
__global__ void k_scatter(const void* __restrict__ ei_raw) {
    int e = blockIdx.x * blockDim.x + threadIdx.x;
    if (e >= N_EDGES) return;
    int r, c;
    if (g_is64) {
        const long long* ei = (const long long*)ei_raw;
        r = (int)ei[e]; c = (int)ei[N_EDGES + e];
    } else {
        const int* ei = (const int*)ei_raw;
        r = ei[e]; c = ei[N_EDGES + e];
    }
    int slot = atomicAdd(&g_cnt[r], 1);
    if (slot < CAP) g_bcol[r * CAP + slot] = c;
}

// ---------------- gather attention (fp16 k/v) + residual + LN1 ----------------
__global__ __launch_bounds__(256) void k_gather(const float* __restrict__ x,
                                                const float* __restrict__ lg,
                                                const float* __restrict__ lb) {
    int t = threadIdx.x;
    int n = blockIdx.x * 32 + (t >> 3);
    int h = t & 7;
    const int base = n * 64 + h * 8;
    const float4* qp = (const float4*)(g_q + base);
    float4 q0 = qp[0], q1 = qp[1];

    int deg = g_cnt[n];
    if (deg > CAP) deg = CAP;

    float den = 0.f;
    float4 a0 = make_float4(0.f, 0.f, 0.f, 0.f);
    float4 a1 = make_float4(0.f, 0.f, 0.f, 0.f);

    const int* bp = g_bcol + n * CAP;
    int cnext = (deg > 0) ? bp[0] : 0;
    for (int s = 0; s < deg; s++) {
        int c = cnext;
        cnext = (s + 1 < deg) ? bp[s + 1] : 0;
        uint4 kr = *(const uint4*)(g_kh + c * 64 + h * 8);
        uint4 vr = *(const uint4*)(g_vh + c * 64 + h * 8);
        float2 k0 = __half22float2(*(__half2*)&kr.x);
        float2 k1 = __half22float2(*(__half2*)&kr.y);
        float2 k2 = __half22float2(*(__half2*)&kr.z);
        float2 k3 = __half22float2(*(__half2*)&kr.w);
        float dot = q0.x * k0.x + q0.y * k0.y + q0.z * k1.x + q0.w * k1.y
                  + q1.x * k2.x + q1.y * k2.y + q1.z * k3.x + q1.w * k3.y;
        float ew = __expf(dot * 0.125f);
        den += ew;
        float2 v0 = __half22float2(*(__half2*)&vr.x);
        float2 v1 = __half22float2(*(__half2*)&vr.y);
        float2 v2 = __half22float2(*(__half2*)&vr.z);
        float2 v3 = __half22float2(*(__half2*)&vr.w);
        a0.x += ew * v0.x; a0.y += ew * v0.y; a0.z += ew * v1.x; a0.w += ew * v1.y;
        a1.x += ew * v2.x; a1.y += ew * v2.y; a1.z += ew * v3.x; a1.w += ew * v3.y;
    }
    float inv = (den > 0.f) ? (1.f / den) : 0.f;

    const float4* xp = (const float4*)(x + base);
    float4 x0 = xp[0], x1 = xp[1];
    float s_[8];
    s_[0] = x0.x + a0.x * inv; s_[1] = x0.y + a0.y * inv;
    s_[2] = x0.z + a0.z * inv; s_[3] = x0.w + a0.w * inv;
    s_[4] = x1.x + a1.x * inv; s_[5] = x1.y + a1.y * inv;
    s_[6] = x1.z + a1.z * inv; s_[7] = x1.w + a1.w * inv;
    float sum = 0.f, sq = 0.f;
#pragma unroll
    for (int j = 0; j < 8; j++) { sum += s_[j]; sq += s_[j] * s_[j]; }
#pragma unroll
    for (int o = 4; o; o >>= 1) {
        sum += __shfl_xor_sync(0xffffffffu, sum, o);
        sq  += __shfl_xor_sync(0xffffffffu, sq, o);
    }
    float mean = sum * (1.f / 64.f);
    float var = sq * (1.f / 64.f) - mean * mean;
    float rstd = rsqrtf(var + LN_EPS);
    float4 y0, y1;
    int c0 = h * 8;
    y0.x = (s_[0] - mean) * rstd * lg[c0 + 0] + lb[c0 + 0];
    y0.y = (s_[1] - mean) * rstd * lg[c0 + 1] + lb[c0 + 1];
    y0.z = (s_[2] - mean) * rstd * lg[c0 + 2] + lb[c0 + 2];
    y0.w = (s_[3] - mean) * rstd * lg[c0 + 3] + lb[c0 + 3];
    y1.x = (s_[4] - mean) * rstd * lg[c0 + 4] + lb[c0 + 4];
    y1.y = (s_[5] - mean) * rstd * lg[c0 + 5] + lb[c0 + 5];
    y1.z = (s_[6] - mean) * rstd * lg[c0 + 6] + lb[c0 + 6];
    y1.w = (s_[7] - mean) * rstd * lg[c0 + 7] + lb[c0 + 7];
    float4* op = (float4*)(g_x1 + base);
    op[0] = y0; op[1] = y1;
}

// ---------------- fused FFN: 32-node tiles, vectorized epilogue (stride 72) ----------------
__global__ __launch_bounds__(256, 2) void k_ffn(const float* __restrict__ w1,
                                                const float* __restrict__ b1,
                                                const float* __restrict__ w2,
                                                const float* __restrict__ b2,
                                                const float* __restrict__ lg,
                                                const float* __restrict__ lb,
                                                float* __restrict__ out) {
    __shared__ __align__(16) __half xh[32 * 72];        // 4.5 kB
    __shared__ __align__(16) float  xr[32 * 72];        // 9.0 kB
    __shared__ __align__(16) __half hs[32 * 264];       // 16.5 kB
    __shared__ __align__(16) float  osum[2][32 * 72];   // 18.0 kB  (total 48 kB)
    int t = threadIdx.x;
    int wp = t >> 5, l = t & 31, gid = l >> 2, tig = l & 3;
    int kw = wp >> 2, nw2 = wp & 3;
    int lmrow = ((l >> 3) & 1) * 8 + (l & 7);
    int lmk = (l >> 4) * 8;
    int lmoff72  = lmrow * 72  + lmk;
    int lmoff264 = lmrow * 264 + lmk;

    unsigned b1fr[4][4][2];
#pragma unroll
    for (int nt = 0; nt < 4; nt++)
#pragma unroll
        for (int ks = 0; ks < 4; ks++)
            ldbh(b1fr[nt][ks], w1, ks * 16 + 2 * tig, wp * 32 + nt * 8 + gid, 256);
    float2 bias1[4];
#pragma unroll
    for (int nt = 0; nt < 4; nt++) {
        int ch0 = wp * 32 + nt * 8 + 2 * tig;
        bias1[nt] = make_float2(b1[ch0], b1[ch0 + 1]);
    }
    unsigned b2fr[2][8][2];
#pragma unroll
    for (int nt = 0; nt < 2; nt++)
#pragma unroll
        for (int ks = 0; ks < 8; ks++)
            ldbh(b2fr[nt][ks], w2, kw * 128 + ks * 16 + 2 * tig, nw2 * 16 + nt * 8 + gid, 64);
    int oh = t & 7;

    const int ngrp = N_NODES / 32;
    const int stride = gridDim.x;
    int p = blockIdx.x;
    if (p < ngrp) {
#pragma unroll
        for (int j = 0; j < 2; j++) {
            int i = t + j * 256;
            float4 v = ((const float4*)(g_x1 + p * 2048))[i];
            *(float4*)&xr[(i >> 4) * 72 + (i & 15) * 4] = v;
            __half2 hA = __floats2half2_rn(v.x, v.y), hB = __floats2half2_rn(v.z, v.w);
            *(uint2*)&xh[(i >> 4) * 72 + (i & 15) * 4] =
                make_uint2(*(unsigned*)&hA, *(unsigned*)&hB);
        }
    }
    __syncthreads();
    for (; p < ngrp; p += stride) {
        int pn = p + stride;
        float4 nx0, nx1;
        if (pn < ngrp) {
            nx0 = ((const float4*)(g_x1 + pn * 2048))[t];
            nx1 = ((const float4*)(g_x1 + pn * 2048))[t + 256];
        }
        int n0 = p * 32;
        // GEMM1
#pragma unroll
        for (int mh = 0; mh < 2; mh++) {
            float acc[4][4] = {{0.f,0.f,0.f,0.f},{0.f,0.f,0.f,0.f},
                               {0.f,0.f,0.f,0.f},{0.f,0.f,0.f,0.f}};
            const __half* tb = &xh[(mh * 16) * 72] + lmoff72;
#pragma unroll
            for (int ks = 0; ks < 4; ks++) {
                unsigned a[4];
                ldmat4(a, tb + ks * 16);
                mma16h(acc[0], a, b1fr[0][ks]);
                mma16h(acc[1], a, b1fr[1][ks]);
                mma16h(acc[2], a, b1fr[2][ks]);
                mma16h(acc[3], a, b1fr[3][ks]);
            }
            int r0 = mh * 16 + gid;
#pragma unroll
            for (int nt = 0; nt < 4; nt++) {
                int ch0 = wp * 32 + nt * 8 + 2 * tig;
                *(__half2*)&hs[r0 * 264 + ch0] =
                    __floats2half2_rn(fmaxf(acc[nt][0] + bias1[nt].x, 0.f),
                                      fmaxf(acc[nt][1] + bias1[nt].y, 0.f));
                *(__half2*)&hs[(r0 + 8) * 264 + ch0] =
                    __floats2half2_rn(fmaxf(acc[nt][2] + bias1[nt].x, 0.f),
                                      fmaxf(acc[nt][3] + bias1[nt].y, 0.f));
            }
        }
        __syncthreads();
        // GEMM2
#pragma unroll
        for (int mh = 0; mh < 2; mh++) {
            float acc[2][4] = {{0.f,0.f,0.f,0.f},{0.f,0.f,0.f,0.f}};
            const __half* tb = &hs[(mh * 16) * 264 + kw * 128] + lmoff264;
#pragma unroll
            for (int ks = 0; ks < 8; ks++) {
                unsigned a[4];
                ldmat4(a, tb + ks * 16);
                mma16h(acc[0], a, b2fr[0][ks]);
                mma16h(acc[1], a, b2fr[1][ks]);
            }
            int r0 = mh * 16 + gid;
#pragma unroll
            for (int nt = 0; nt < 2; nt++) {
                int ch0 = nw2 * 16 + nt * 8 + 2 * tig;
                *(float2*)&osum[kw][r0 * 72 + ch0]       = make_float2(acc[nt][0], acc[nt][1]);
                *(float2*)&osum[kw][(r0 + 8) * 72 + ch0] = make_float2(acc[nt][2], acc[nt][3]);
            }
        }
        __syncthreads();
        // epilogue (vectorized)
        {
            int node = t >> 3;
            int bi = node * 72 + oh * 8;
            float4 xa0 = *(float4*)&xr[bi],      xa1 = *(float4*)&xr[bi + 4];
            float4 oa0 = *(float4*)&osum[0][bi], oa1 = *(float4*)&osum[0][bi + 4];
            float4 ob0 = *(float4*)&osum[1][bi], ob1 = *(float4*)&osum[1][bi + 4];
            float4 b20 = *(const float4*)&b2[oh * 8], b21 = *(const float4*)&b2[oh * 8 + 4];
            float s[8];
            s[0] = xa0.x + oa0.x + ob0.x + b20.x;
            s[1] = xa0.y + oa0.y + ob0.y + b20.y;
            s[2] = xa0.z + oa0.z + ob0.z + b20.z;
            s[3] = xa0.w + oa0.w + ob0.w + b20.w;
            s[4] = xa1.x + oa1.x + ob1.x + b21.x;
            s[5] = xa1.y + oa1.y + ob1.y + b21.y;
            s[6] = xa1.z + oa1.z + ob1.z + b21.z;
            s[7] = xa1.w + oa1.w + ob1.w + b21.w;
            float sum = 0.f, sq = 0.f;
#pragma unroll
            for (int j = 0; j < 8; j++) { sum += s[j]; sq += s[j] * s[j]; }
#pragma unroll
            for (int o = 4; o; o >>= 1) {
                sum += __shfl_xor_sync(0xffffffffu, sum, o);
                sq  += __shfl_xor_sync(0xffffffffu, sq, o);
            }
            float mean = sum * (1.f / 64.f);
            float var = sq * (1.f / 64.f) - mean * mean;
            float rstd = rsqrtf(var + LN_EPS);
            float4 lg0 = *(const float4*)&lg[oh * 8], lg1 = *(const float4*)&lg[oh * 8 + 4];
            float4 lb0 = *(const float4*)&lb[oh * 8], lb1 = *(const float4*)&lb[oh * 8 + 4];
            float4 o0, o1;
            o0.x = (s[0] - mean) * rstd * lg0.x + lb0.x;
            o0.y = (s[1] - mean) * rstd * lg0.y + lb0.y;
            o0.z = (s[2] - mean) * rstd * lg0.z + lb0.z;
            o0.w = (s[3] - mean) * rstd * lg0.w + lb0.w;
            o1.x = (s[4] - mean) * rstd * lg1.x + lb1.x;
            o1.y = (s[5] - mean) * rstd * lg1.y + lb1.y;
            o1.z = (s[6] - mean) * rstd * lg1.z + lb1.z;
            o1.w = (s[7] - mean) * rstd * lg1.w + lb1.w;
            *(float4*)&out[(n0 + node) * 64 + oh * 8]     = o0;
            *(float4*)&out[(n0 + node) * 64 + oh * 8 + 4] = o1;
        }
        __syncthreads();
        if (pn < ngrp) {
#pragma unroll
            for (int j = 0; j < 2; j++) {
                int i = t + j * 256;
                float4 v = (j == 0) ? nx0 : nx1;
                *(float4*)&xr[(i >> 4) * 72 + (i & 15) * 4] = v;
                __half2 hA = __floats2half2_rn(v.x, v.y), hB = __floats2half2_rn(v.z, v.w);
                *(uint2*)&xh[(i >> 4) * 72 + (i & 15) * 4] =
                    make_uint2(*(unsigned*)&hA, *(unsigned*)&hB);
            }
        }
        __syncthreads();
    }
}

extern "C" void kernel_launch(void* const* d_in, const int* in_sizes, int n_in,
                              void* d_out, int out_size) {
    const float* x      = (const float*)d_in[0];
    const void*  ei     = d_in[1];
    const float* attn_w = (const float*)d_in[2];
    const float* attn_b = (const float*)d_in[3];
    const float* w1     = (const float*)d_in[4];
    const float* b1     = (const float*)d_in[5];
    const float* w2     = (const float*)d_in[6];
    const float* b2     = (const float*)d_in[7];
    const float* ln1_g  = (const float*)d_in[8];
    const float* ln1_b  = (const float*)d_in[9];
    const float* ln2_g  = (const float*)d_in[10];
    const float* ln2_b  = (const float*)d_in[11];
    float* out = (float*)d_out;

    // one-time side-stream/event handles (created on the uncaptured correctness
    // call; reused identically on every call -> deterministic work each launch)
    static cudaStream_t s2 = 0;
    static cudaEvent_t evF = 0, evJ = 0;
    static int tried = 0;
    if (!tried) {
        tried = 1;
        if (cudaStreamCreateWithFlags(&s2, cudaStreamNonBlocking) != cudaSuccess) s2 = 0;
        if (s2 && cudaEventCreateWithFlags(&evF, cudaEventDisableTiming) != cudaSuccess) s2 = 0;
        if (s2 && cudaEventCreateWithFlags(&evJ, cudaEventDisableTiming) != cudaSuccess) s2 = 0;
    }

    k_init<<<(N_NODES + 1023) / 1024, 1024>>>(ei);
    if (s2) {
        // fork: scatter (ei only) runs concurrently with qkv (x only)
        cudaEventRecord(evF, 0);
        cudaStreamWaitEvent(s2, evF, 0);
        k_scatter<<<N_EDGES / 256, 256, 0, s2>>>(ei);
        k_qkv<<<296, 256>>>(x, attn_w, attn_b);
        cudaEventRecord(evJ, s2);
        cudaStreamWaitEvent(0, evJ, 0);
    } else {
        k_qkv<<<296, 256>>>(x, attn_w, attn_b);
        k_scatter<<<N_EDGES / 256, 256>>>(ei);
    }
    k_gather<<<N_NODES / 32, 256>>>(x, ln1_g, ln1_b);
    k_ffn<<<296, 256>>>(w1, b1, w2, b2, ln2_g, ln2_b, out);
}

// round 17
// speedup vs baseline: 4.9347x; 1.0510x over previous
#include <cuda_runtime.h>
#include <cuda_bf16.h>
#include <cuda_fp16.h>

#define N_NODES 100000
#define N_EDGES 1600000
#define EMBED 64
#define HEADS 8
#define FFN_DIM 256
#define LN_EPS 1e-5f
#define CAP 128

typedef unsigned long long u64;

// ---------------- fp16 mma.sync m16n8k16 ----------------
__device__ __forceinline__ void mma16h(float* acc, const unsigned* a, const unsigned* b) {
    asm volatile("mma.sync.aligned.m16n8k16.row.col.f32.f16.f16.f32 "
                 "{%0,%1,%2,%3},{%4,%5,%6,%7},{%8,%9},{%0,%1,%2,%3};"
                 : "+f"(acc[0]), "+f"(acc[1]), "+f"(acc[2]), "+f"(acc[3])
                 : "r"(a[0]), "r"(a[1]), "r"(a[2]), "r"(a[3]), "r"(b[0]), "r"(b[1]));
}
__device__ __forceinline__ void ldmat4(unsigned a[4], const __half* p) {
    unsigned addr = (unsigned)__cvta_generic_to_shared(p);
    asm volatile("ldmatrix.sync.aligned.m8n8.x4.shared.b16 {%0,%1,%2,%3}, [%4];"
                 : "=r"(a[0]), "=r"(a[1]), "=r"(a[2]), "=r"(a[3]) : "r"(addr));
}
__device__ __forceinline__ void ldbh(unsigned b[2], const float* W, int k0, int col, int ld) {
    __half2 h0 = __floats2half2_rn(W[(k0    ) * ld + col], W[(k0 + 1) * ld + col]);
    __half2 h1 = __floats2half2_rn(W[(k0 + 8) * ld + col], W[(k0 + 9) * ld + col]);
    b[0] = *(unsigned*)&h0;
    b[1] = *(unsigned*)&h1;
}

// ---------------- scratch ----------------
__device__ __half g_qh[N_NODES * EMBED];
__device__ __half g_kh[N_NODES * EMBED];
__device__ __half g_vh[N_NODES * EMBED];
__device__ float  g_x1[N_NODES * EMBED];
__device__ int    g_cnt[N_NODES];
__device__ int    g_bcol[N_NODES * CAP];
__device__ int    g_is64;

// ---------------- init: zero counters + index dtype probe ----------------
__global__ void k_init(const void* __restrict__ ei) {
    int i = blockIdx.x * blockDim.x + threadIdx.x;
    if (i < N_NODES) g_cnt[i] = 0;
    if (i == 0) {
        const unsigned* wr = (const unsigned*)ei;
        int is64 = 1;
        for (int q = 1; q < 256; q += 2) if (wr[q] != 0u) { is64 = 0; break; }
        g_is64 = is64;
    }
}

// ---------------- QKV: fp16 mma + ldmatrix; q/k/v all fp16 ----------------
__global__ __launch_bounds__(256, 2) void k_qkv(const float* __restrict__ x,
                                                const float* __restrict__ w,
                                                const float* __restrict__ b) {
    int t = threadIdx.x;
    __shared__ __align__(16) __half xh[2][32 * 72];
    int wp = t >> 5, l = t & 31, gid = l >> 2, tig = l & 3;
    int nb = wp * 24;
    int lmoff72 = (((l >> 3) & 1) * 8 + (l & 7)) * 72 + (l >> 4) * 8;
    unsigned bfr[3][4][2];
#pragma unroll
    for (int nt = 0; nt < 3; nt++)
#pragma unroll
        for (int ks = 0; ks < 4; ks++)
            ldbh(bfr[nt][ks], w, ks * 16 + 2 * tig, nb + nt * 8 + gid, 192);
    int seg[3], doff[3]; float2 bias[3];
#pragma unroll
    for (int nt = 0; nt < 3; nt++) {
        int ch0 = nb + nt * 8 + 2 * tig;
        int h = ch0 / 24, r = ch0 % 24;
        seg[nt] = (r < 8) ? 0 : ((r < 16) ? 1 : 2);
        doff[nt] = h * 8 + (r & 7);
        bias[nt] = make_float2(b[ch0], b[ch0 + 1]);
    }

    const int ngrp = N_NODES / 32;
    const int stride = gridDim.x;
    int p = blockIdx.x;
    if (p < ngrp) {
#pragma unroll
        for (int j = 0; j < 2; j++) {
            int i = t + j * 256;
            float4 v = ((const float4*)(x + p * 2048))[i];
            __half2 hA = __floats2half2_rn(v.x, v.y), hB = __floats2half2_rn(v.z, v.w);
            *(uint2*)&xh[0][(i >> 4) * 72 + (i & 15) * 4] =
                make_uint2(*(unsigned*)&hA, *(unsigned*)&hB);
        }
    }
    __syncthreads();
    for (int it = 0; p < ngrp; p += stride, it ^= 1) {
        int pn = p + stride;
        float4 nx0, nx1;
        if (pn < ngrp) {
            nx0 = ((const float4*)(x + pn * 2048))[t];
            nx1 = ((const float4*)(x + pn * 2048))[t + 256];
        }
        int n0 = p * 32;
#pragma unroll
        for (int mh = 0; mh < 2; mh++) {
            float acc[3][4] = {{0.f,0.f,0.f,0.f},{0.f,0.f,0.f,0.f},{0.f,0.f,0.f,0.f}};
            const __half* tb = &xh[it][(mh * 16) * 72] + lmoff72;
#pragma unroll
            for (int ks = 0; ks < 4; ks++) {
                unsigned a[4];
                ldmat4(a, tb + ks * 16);
                mma16h(acc[0], a, bfr[0][ks]);
                mma16h(acc[1], a, bfr[1][ks]);
                mma16h(acc[2], a, bfr[2][ks]);
            }
            int na = n0 + mh * 16 + gid;
#pragma unroll
            for (int nt = 0; nt < 3; nt++) {
                __half* base = (seg[nt] == 0) ? g_qh : ((seg[nt] == 1) ? g_kh : g_vh);
                *(__half2*)&base[na * 64 + doff[nt]] =
                    __floats2half2_rn(acc[nt][0] + bias[nt].x, acc[nt][1] + bias[nt].y);
                *(__half2*)&base[(na + 8) * 64 + doff[nt]] =
                    __floats2half2_rn(acc[nt][2] + bias[nt].x, acc[nt][3] + bias[nt].y);
            }
        }
        if (pn < ngrp) {
            __half2 hA = __floats2half2_rn(nx0.x, nx0.y), hB = __floats2half2_rn(nx0.z, nx0.w);
            *(uint2*)&xh[it ^ 1][(t >> 4) * 72 + (t & 15) * 4] =
                make_uint2(*(unsigned*)&hA, *(unsigned*)&hB);
            int i = t + 256;
            hA = __floats2half2_rn(nx1.x, nx1.y); hB = __floats2half2_rn(nx1.z, nx1.w);
            *(uint2*)&xh[it ^ 1][(i >> 4) * 72 + (i & 15) * 4] =
                make_uint2(*(unsigned*)&hA, *(unsigned*)&hB);
        }
        __syncthreads();
    }
}

// ---------------- bucket scatter ----------------
__global__ void k_scatter(const void* __restrict__ ei_raw) {
    int e = blockIdx.x * blockDim.x + threadIdx.x;
    if (e >= N_EDGES) return;
    int r, c;
    if (g_is64) {
        const long long* ei = (const long long*)ei_raw;
        r = (int)ei[e]; c = (int)ei[N_EDGES + e];
    } else {
        const int* ei = (const int*)ei_raw;
        r = ei[e]; c = ei[N_EDGES + e];
    }
    int slot = atomicAdd(&g_cnt[r], 1);
    if (slot < CAP) g_bcol[r * CAP + slot] = c;
}

// ---------------- gather attention: fp16 HFMA2 edge math + residual + LN1 ----------------
__global__ __launch_bounds__(256) void k_gather(const float* __restrict__ x,
                                                const float* __restrict__ lg,
                                                const float* __restrict__ lb) {
    int t = threadIdx.x;
    int n = blockIdx.x * 32 + (t >> 3);
    int h = t & 7;
    const int base = n * 64 + h * 8;
    uint4 qr = *(const uint4*)(g_qh + base);
    __half2 q0 = *(__half2*)&qr.x, q1 = *(__half2*)&qr.y;
    __half2 q2 = *(__half2*)&qr.z, q3 = *(__half2*)&qr.w;

    int deg = g_cnt[n];
    if (deg > CAP) deg = CAP;

    float den = 0.f;
    __half2 z = __float2half2_rn(0.f);
    __half2 a0 = z, a1 = z, a2 = z, a3 = z;

    const int* bp = g_bcol + n * CAP;
    int cnext = (deg > 0) ? bp[0] : 0;
    for (int s = 0; s < deg; s++) {
        int c = cnext;
        cnext = (s + 1 < deg) ? bp[s + 1] : 0;
        uint4 kr = *(const uint4*)(g_kh + c * 64 + h * 8);
        uint4 vr = *(const uint4*)(g_vh + c * 64 + h * 8);
        __half2 d = __hmul2(q0, *(__half2*)&kr.x);
        d = __hfma2(q1, *(__half2*)&kr.y, d);
        d = __hfma2(q2, *(__half2*)&kr.z, d);
        d = __hfma2(q3, *(__half2*)&kr.w, d);
        float dot = __low2float(d) + __high2float(d);
        float ew = __expf(dot * 0.125f);
        den += ew;
        __half2 ewh = __float2half2_rn(ew);
        a0 = __hfma2(ewh, *(__half2*)&vr.x, a0);
        a1 = __hfma2(ewh, *(__half2*)&vr.y, a1);
        a2 = __hfma2(ewh, *(__half2*)&vr.z, a2);
        a3 = __hfma2(ewh, *(__half2*)&vr.w, a3);
    }
    float inv = (den > 0.f) ? (1.f / den) : 0.f;

    float2 f0 = __half22float2(a0), f1 = __half22float2(a1);
    float2 f2 = __half22float2(a2), f3 = __half22float2(a3);
    const float4* xp = (const float4*)(x + base);
    float4 x0 = xp[0], x1 = xp[1];
    float s_[8];
    s_[0] = x0.x + f0.x * inv; s_[1] = x0.y + f0.y * inv;
    s_[2] = x0.z + f1.x * inv; s_[3] = x0.w + f1.y * inv;
    s_[4] = x1.x + f2.x * inv; s_[5] = x1.y + f2.y * inv;
    s_[6] = x1.z + f3.x * inv; s_[7] = x1.w + f3.y * inv;
    float sum = 0.f, sq = 0.f;
#pragma unroll
    for (int j = 0; j < 8; j++) { sum += s_[j]; sq += s_[j] * s_[j]; }
#pragma unroll
    for (int o = 4; o; o >>= 1) {
        sum += __shfl_xor_sync(0xffffffffu, sum, o);
        sq  += __shfl_xor_sync(0xffffffffu, sq, o);
    }
    float mean = sum * (1.f / 64.f);
    float var = sq * (1.f / 64.f) - mean * mean;
    float rstd = rsqrtf(var + LN_EPS);
    float4 y0, y1;
    int c0 = h * 8;
    y0.x = (s_[0] - mean) * rstd * lg[c0 + 0] + lb[c0 + 0];
    y0.y = (s_[1] - mean) * rstd * lg[c0 + 1] + lb[c0 + 1];
    y0.z = (s_[2] - mean) * rstd * lg[c0 + 2] + lb[c0 + 2];
    y0.w = (s_[3] - mean) * rstd * lg[c0 + 3] + lb[c0 + 3];
    y1.x = (s_[4] - mean) * rstd * lg[c0 + 4] + lb[c0 + 4];
    y1.y = (s_[5] - mean) * rstd * lg[c0 + 5] + lb[c0 + 5];
    y1.z = (s_[6] - mean) * rstd * lg[c0 + 6] + lb[c0 + 6];
    y1.w = (s_[7] - mean) * rstd * lg[c0 + 7] + lb[c0 + 7];
    float4* op = (float4*)(g_x1 + base);
    op[0] = y0; op[1] = y1;
}

// ---------------- fused FFN: 32-node tiles, vectorized epilogue ----------------
__global__ __launch_bounds__(256, 2) void k_ffn(const float* __restrict__ w1,
                                                const float* __restrict__ b1,
                                                const float* __restrict__ w2,
                                                const float* __restrict__ b2,
                                                const float* __restrict__ lg,
                                                const float* __restrict__ lb,
                                                float* __restrict__ out) {
    __shared__ __align__(16) __half xh[32 * 72];
    __shared__ __align__(16) float  xr[32 * 72];
    __shared__ __align__(16) __half hs[32 * 264];
    __shared__ __align__(16) float  osum[2][32 * 72];
    int t = threadIdx.x;
    int wp = t >> 5, l = t & 31, gid = l >> 2, tig = l & 3;
    int kw = wp >> 2, nw2 = wp & 3;
    int lmrow = ((l >> 3) & 1) * 8 + (l & 7);
    int lmk = (l >> 4) * 8;
    int lmoff72  = lmrow * 72  + lmk;
    int lmoff264 = lmrow * 264 + lmk;

    unsigned b1fr[4][4][2];
#pragma unroll
    for (int nt = 0; nt < 4; nt++)
#pragma unroll
        for (int ks = 0; ks < 4; ks++)
            ldbh(b1fr[nt][ks], w1, ks * 16 + 2 * tig, wp * 32 + nt * 8 + gid, 256);
    float2 bias1[4];
#pragma unroll
    for (int nt = 0; nt < 4; nt++) {
        int ch0 = wp * 32 + nt * 8 + 2 * tig;
        bias1[nt] = make_float2(b1[ch0], b1[ch0 + 1]);
    }
    unsigned b2fr[2][8][2];
#pragma unroll
    for (int nt = 0; nt < 2; nt++)
#pragma unroll
        for (int ks = 0; ks < 8; ks++)
            ldbh(b2fr[nt][ks], w2, kw * 128 + ks * 16 + 2 * tig, nw2 * 16 + nt * 8 + gid, 64);
    int oh = t & 7;

    const int ngrp = N_NODES / 32;
    const int stride = gridDim.x;
    int p = blockIdx.x;
    if (p < ngrp) {
#pragma unroll
        for (int j = 0; j < 2; j++) {
            int i = t + j * 256;
            float4 v = ((const float4*)(g_x1 + p * 2048))[i];
            *(float4*)&xr[(i >> 4) * 72 + (i & 15) * 4] = v;
            __half2 hA = __floats2half2_rn(v.x, v.y), hB = __floats2half2_rn(v.z, v.w);
            *(uint2*)&xh[(i >> 4) * 72 + (i & 15) * 4] =
                make_uint2(*(unsigned*)&hA, *(unsigned*)&hB);
        }
    }
    __syncthreads();
    for (; p < ngrp; p += stride) {
        int pn = p + stride;
        float4 nx0, nx1;
        if (pn < ngrp) {
            nx0 = ((const float4*)(g_x1 + pn * 2048))[t];
            nx1 = ((const float4*)(g_x1 + pn * 2048))[t + 256];
        }
        int n0 = p * 32;
        // GEMM1
#pragma unroll
        for (int mh = 0; mh < 2; mh++) {
            float acc[4][4] = {{0.f,0.f,0.f,0.f},{0.f,0.f,0.f,0.f},
                               {0.f,0.f,0.f,0.f},{0.f,0.f,0.f,0.f}};
            const __half* tb = &xh[(mh * 16) * 72] + lmoff72;
#pragma unroll
            for (int ks = 0; ks < 4; ks++) {
                unsigned a[4];
                ldmat4(a, tb + ks * 16);
                mma16h(acc[0], a, b1fr[0][ks]);
                mma16h(acc[1], a, b1fr[1][ks]);
                mma16h(acc[2], a, b1fr[2][ks]);
                mma16h(acc[3], a, b1fr[3][ks]);
            }
            int r0 = mh * 16 + gid;
#pragma unroll
            for (int nt = 0; nt < 4; nt++) {
                int ch0 = wp * 32 + nt * 8 + 2 * tig;
                *(__half2*)&hs[r0 * 264 + ch0] =
                    __floats2half2_rn(fmaxf(acc[nt][0] + bias1[nt].x, 0.f),
                                      fmaxf(acc[nt][1] + bias1[nt].y, 0.f));
                *(__half2*)&hs[(r0 + 8) * 264 + ch0] =
                    __floats2half2_rn(fmaxf(acc[nt][2] + bias1[nt].x, 0.f),
                                      fmaxf(acc[nt][3] + bias1[nt].y, 0.f));
            }
        }
        __syncthreads();
        // GEMM2
#pragma unroll
        for (int mh = 0; mh < 2; mh++) {
            float acc[2][4] = {{0.f,0.f,0.f,0.f},{0.f,0.f,0.f,0.f}};
            const __half* tb = &hs[(mh * 16) * 264 + kw * 128] + lmoff264;
#pragma unroll
            for (int ks = 0; ks < 8; ks++) {
                unsigned a[4];
                ldmat4(a, tb + ks * 16);
                mma16h(acc[0], a, b2fr[0][ks]);
                mma16h(acc[1], a, b2fr[1][ks]);
            }
            int r0 = mh * 16 + gid;
#pragma unroll
            for (int nt = 0; nt < 2; nt++) {
                int ch0 = nw2 * 16 + nt * 8 + 2 * tig;
                *(float2*)&osum[kw][r0 * 72 + ch0]       = make_float2(acc[nt][0], acc[nt][1]);
                *(float2*)&osum[kw][(r0 + 8) * 72 + ch0] = make_float2(acc[nt][2], acc[nt][3]);
            }
        }
        __syncthreads();
        // epilogue (vectorized)
        {
            int node = t >> 3;
            int bi = node * 72 + oh * 8;
            float4 xa0 = *(float4*)&xr[bi],      xa1 = *(float4*)&xr[bi + 4];
            float4 oa0 = *(float4*)&osum[0][bi], oa1 = *(float4*)&osum[0][bi + 4];
            float4 ob0 = *(float4*)&osum[1][bi], ob1 = *(float4*)&osum[1][bi + 4];
            float4 b20 = *(const float4*)&b2[oh * 8], b21 = *(const float4*)&b2[oh * 8 + 4];
            float s[8];
            s[0] = xa0.x + oa0.x + ob0.x + b20.x;
            s[1] = xa0.y + oa0.y + ob0.y + b20.y;
            s[2] = xa0.z + oa0.z + ob0.z + b20.z;
            s[3] = xa0.w + oa0.w + ob0.w + b20.w;
            s[4] = xa1.x + oa1.x + ob1.x + b21.x;
            s[5] = xa1.y + oa1.y + ob1.y + b21.y;
            s[6] = xa1.z + oa1.z + ob1.z + b21.z;
            s[7] = xa1.w + oa1.w + ob1.w + b21.w;
            float sum = 0.f, sq = 0.f;
#pragma unroll
            for (int j = 0; j < 8; j++) { sum += s[j]; sq += s[j] * s[j]; }
#pragma unroll
            for (int o = 4; o; o >>= 1) {
                sum += __shfl_xor_sync(0xffffffffu, sum, o);
                sq  += __shfl_xor_sync(0xffffffffu, sq, o);
            }
            float mean = sum * (1.f / 64.f);
            float var = sq * (1.f / 64.f) - mean * mean;
            float rstd = rsqrtf(var + LN_EPS);
            float4 lg0 = *(const float4*)&lg[oh * 8], lg1 = *(const float4*)&lg[oh * 8 + 4];
            float4 lb0 = *(const float4*)&lb[oh * 8], lb1 = *(const float4*)&lb[oh * 8 + 4];
            float4 o0, o1;
            o0.x = (s[0] - mean) * rstd * lg0.x + lb0.x;
            o0.y = (s[1] - mean) * rstd * lg0.y + lb0.y;
            o0.z = (s[2] - mean) * rstd * lg0.z + lb0.z;
            o0.w = (s[3] - mean) * rstd * lg0.w + lb0.w;
            o1.x = (s[4] - mean) * rstd * lg1.x + lb1.x;
            o1.y = (s[5] - mean) * rstd * lg1.y + lb1.y;
            o1.z = (s[6] - mean) * rstd * lg1.z + lb1.z;
            o1.w = (s[7] - mean) * rstd * lg1.w + lb1.w;
            *(float4*)&out[(n0 + node) * 64 + oh * 8]     = o0;
            *(float4*)&out[(n0 + node) * 64 + oh * 8 + 4] = o1;
        }
        __syncthreads();
        if (pn < ngrp) {
#pragma unroll
            for (int j = 0; j < 2; j++) {
                int i = t + j * 256;
                float4 v = (j == 0) ? nx0 : nx1;
                *(float4*)&xr[(i >> 4) * 72 + (i & 15) * 4] = v;
                __half2 hA = __floats2half2_rn(v.x, v.y), hB = __floats2half2_rn(v.z, v.w);
                *(uint2*)&xh[(i >> 4) * 72 + (i & 15) * 4] =
                    make_uint2(*(unsigned*)&hA, *(unsigned*)&hB);
            }
        }
        __syncthreads();
    }
}

extern "C" void kernel_launch(void* const* d_in, const int* in_sizes, int n_in,
                              void* d_out, int out_size) {
    const float* x      = (const float*)d_in[0];
    const void*  ei     = d_in[1];
    const float* attn_w = (const float*)d_in[2];
    const float* attn_b = (const float*)d_in[3];
    const float* w1     = (const float*)d_in[4];
    const float* b1     = (const float*)d_in[5];
    const float* w2     = (const float*)d_in[6];
    const float* b2     = (const float*)d_in[7];
    const float* ln1_g  = (const float*)d_in[8];
    const float* ln1_b  = (const float*)d_in[9];
    const float* ln2_g  = (const float*)d_in[10];
    const float* ln2_b  = (const float*)d_in[11];
    float* out = (float*)d_out;

    static cudaStream_t s2 = 0;
    static cudaEvent_t evF = 0, evJ = 0;
    static int tried = 0;
    if (!tried) {
        tried = 1;
        if (cudaStreamCreateWithFlags(&s2, cudaStreamNonBlocking) != cudaSuccess) s2 = 0;
        if (s2 && cudaEventCreateWithFlags(&evF, cudaEventDisableTiming) != cudaSuccess) s2 = 0;
        if (s2 && cudaEventCreateWithFlags(&evJ, cudaEventDisableTiming) != cudaSuccess) s2 = 0;
    }

    k_init<<<(N_NODES + 1023) / 1024, 1024>>>(ei);
    if (s2) {
        cudaEventRecord(evF, 0);
        cudaStreamWaitEvent(s2, evF, 0);
        k_scatter<<<N_EDGES / 256, 256, 0, s2>>>(ei);
        k_qkv<<<296, 256>>>(x, attn_w, attn_b);
        cudaEventRecord(evJ, s2);
        cudaStreamWaitEvent(0, evJ, 0);
    } else {
        k_qkv<<<296, 256>>>(x, attn_w, attn_b);
        k_scatter<<<N_EDGES / 256, 256>>>(ei);
    }
    k_gather<<<N_NODES / 32, 256>>>(x, ln1_g, ln1_b);
    k_ffn<<<296, 256>>>(w1, b1, w2, b2, ln2_g, ln2_b, out);
}